// round 1
// baseline (speedup 1.0000x reference)
#include <cuda_runtime.h>
#include <math.h>

#define HID  128
#define NCOL 256          // u (128) | v (128) per node
#define MAX_NODES 100000

// Scratch: Y[i*256 + j] = (j<128) ? (A h_i)_j : (B h_i)_{j-128}
// 100000*256*4 = 102.4 MB  (fits entirely in GB300's 126 MB L2)
__device__ float g_Y[(size_t)MAX_NODES * NCOL];

// ---------------------------------------------------------------------------
// K1: Y = H @ G, where G[k][j] is W1 re-packed so that
//     G[k][j]       = W1[j*256 + k]          (u part, j < 128)
//     G[k][128 + j] = W1[j*256 + 128 + k]    (v part)
// Block: 256 threads, tile 64 nodes x 256 cols, thread tile 8x8.
// G (128 KB) + H tile (32 KB) live in dynamic shared.
// ---------------------------------------------------------------------------
__global__ __launch_bounds__(256, 1)
void precompute_kernel(const float* __restrict__ h,
                       const float* __restrict__ W1,
                       int n_nodes)
{
    extern __shared__ float smem[];
    float* Gs = smem;                 // [128][256]
    float* As = smem + HID * NCOL;    // [64][128]
    const int tid = threadIdx.x;

    // --- load & transpose G: thread tid owns output column j = tid ---
    {
        const int j = tid;
        const float* base = (j < HID) ? (W1 + (size_t)j * 2 * HID)
                                      : (W1 + (size_t)(j - HID) * 2 * HID + HID);
        const float4* b4 = reinterpret_cast<const float4*>(base);
        #pragma unroll
        for (int kk = 0; kk < HID / 4; kk++) {
            float4 w = b4[kk];
            Gs[(kk * 4 + 0) * NCOL + j] = w.x;
            Gs[(kk * 4 + 1) * NCOL + j] = w.y;
            Gs[(kk * 4 + 2) * NCOL + j] = w.z;
            Gs[(kk * 4 + 3) * NCOL + j] = w.w;
        }
    }

    // --- load H tile: 64 nodes x 128 floats = 2048 float4 ---
    const int m0 = blockIdx.x * 64;
    {
        const float4* h4 = reinterpret_cast<const float4*>(h);
        float4* A4 = reinterpret_cast<float4*>(As);
        #pragma unroll
        for (int i = tid; i < 64 * (HID / 4); i += 256) {
            int m = m0 + (i >> 5);                 // 32 float4 per row
            float4 val = make_float4(0.f, 0.f, 0.f, 0.f);
            if (m < n_nodes) val = h4[(size_t)m * (HID / 4) + (i & 31)];
            A4[i] = val;
        }
    }
    __syncthreads();

    // thread tile: rows mb..mb+7 (warp-uniform -> smem broadcast),
    // cols nb..nb+3 and 128+nb..128+nb+3
    const int mb = (tid >> 5) * 8;
    const int nb = (tid & 31) * 4;

    float acc[8][8];
    #pragma unroll
    for (int i = 0; i < 8; i++)
        #pragma unroll
        for (int j = 0; j < 8; j++) acc[i][j] = 0.f;

    #pragma unroll 4
    for (int k = 0; k < HID; k++) {
        float4 bq0 = *reinterpret_cast<const float4*>(&Gs[k * NCOL + nb]);
        float4 bq1 = *reinterpret_cast<const float4*>(&Gs[k * NCOL + HID + nb]);
        #pragma unroll
        for (int i = 0; i < 8; i++) {
            float a = As[(mb + i) * HID + k];   // broadcast across warp
            acc[i][0] = fmaf(a, bq0.x, acc[i][0]);
            acc[i][1] = fmaf(a, bq0.y, acc[i][1]);
            acc[i][2] = fmaf(a, bq0.z, acc[i][2]);
            acc[i][3] = fmaf(a, bq0.w, acc[i][3]);
            acc[i][4] = fmaf(a, bq1.x, acc[i][4]);
            acc[i][5] = fmaf(a, bq1.y, acc[i][5]);
            acc[i][6] = fmaf(a, bq1.z, acc[i][6]);
            acc[i][7] = fmaf(a, bq1.w, acc[i][7]);
        }
    }

    #pragma unroll
    for (int i = 0; i < 8; i++) {
        int m = m0 + mb + i;
        if (m < n_nodes) {
            *reinterpret_cast<float4*>(&g_Y[(size_t)m * NCOL + nb]) =
                make_float4(acc[i][0], acc[i][1], acc[i][2], acc[i][3]);
            *reinterpret_cast<float4*>(&g_Y[(size_t)m * NCOL + HID + nb]) =
                make_float4(acc[i][4], acc[i][5], acc[i][6], acc[i][7]);
        }
    }
}

// ---------------------------------------------------------------------------
// K2: one warp per edge (grid-stride).
//   x = relu(u[src] + v[dst] + b1)  -> dot with W2 (warp reduce)
//   -> relu(+b2) -> relu(*W3+b3) -> sigmoid
// Each lane handles 4 contiguous features via float4; Y is L2-resident.
// ---------------------------------------------------------------------------
__global__ __launch_bounds__(256)
void edge_kernel(const int* __restrict__ src,
                 const int* __restrict__ dst,
                 const float* __restrict__ b1,
                 const float* __restrict__ W2,
                 const float* __restrict__ b2,
                 const float* __restrict__ W3,
                 const float* __restrict__ b3,
                 float* __restrict__ out,
                 int E)
{
    const int lane   = threadIdx.x & 31;
    const int wid    = (blockIdx.x * blockDim.x + threadIdx.x) >> 5;
    const int nwarps = (gridDim.x * blockDim.x) >> 5;

    const float4 b1v = reinterpret_cast<const float4*>(b1)[lane];
    const float4 w2v = reinterpret_cast<const float4*>(W2)[lane];
    const float  c2  = b2[0];
    const float  w3  = W3[0];
    const float  c3  = b3[0];

    const float4* Y4 = reinterpret_cast<const float4*>(g_Y);

    for (int e = wid; e < E; e += nwarps) {
        const int s = src[e];
        const int d = dst[e];

        float4 u = Y4[(size_t)s * 64 + lane];        // u part of src node
        float4 v = Y4[(size_t)d * 64 + 32 + lane];   // v part of dst node

        float x0 = fmaxf(u.x + v.x + b1v.x, 0.f);
        float x1 = fmaxf(u.y + v.y + b1v.y, 0.f);
        float x2 = fmaxf(u.z + v.z + b1v.z, 0.f);
        float x3 = fmaxf(u.w + v.w + b1v.w, 0.f);

        float p = x0 * w2v.x + x1 * w2v.y + x2 * w2v.z + x3 * w2v.w;

        #pragma unroll
        for (int off = 16; off > 0; off >>= 1)
            p += __shfl_xor_sync(0xFFFFFFFFu, p, off);

        if (lane == 0) {
            float s2  = fmaxf(p + c2, 0.f);
            float s3  = fmaxf(fmaf(s2, w3, c3), 0.f);
            out[e] = 1.f / (1.f + expf(-s3));
        }
    }
}

// ---------------------------------------------------------------------------
extern "C" void kernel_launch(void* const* d_in, const int* in_sizes, int n_in,
                              void* d_out, int out_size)
{
    const float* h   = (const float*)d_in[0];
    const int*   src = (const int*)  d_in[1];
    const int*   dst = (const int*)  d_in[2];
    const float* W1  = (const float*)d_in[3];
    const float* b1  = (const float*)d_in[4];
    const float* W2  = (const float*)d_in[5];
    const float* b2  = (const float*)d_in[6];
    const float* W3  = (const float*)d_in[7];
    const float* b3  = (const float*)d_in[8];
    float* out = (float*)d_out;

    const int n_nodes = in_sizes[0] / HID;
    const int E       = in_sizes[1];

    const int smem_bytes = (HID * NCOL + 64 * HID) * (int)sizeof(float); // 160 KB
    cudaFuncSetAttribute(precompute_kernel,
                         cudaFuncAttributeMaxDynamicSharedMemorySize, smem_bytes);

    precompute_kernel<<<(n_nodes + 63) / 64, 256, smem_bytes>>>(h, W1, n_nodes);
    edge_kernel<<<4096, 256>>>(src, dst, b1, W2, b2, W3, b3, out, E);
}

// round 3
// speedup vs baseline: 1.3867x; 1.3867x over previous
#include <cuda_runtime.h>
#include <cuda_bf16.h>
#include <math.h>
#include <stdint.h>

#define HID  128
#define NCOL 256
#define MAX_NODES 100000
#define TILE_M 128
#define PADK 136              // bf16 row stride in smem (272B -> conflict-free)

// Y[i*256 + j] = (j<128) ? (A h_i)_j : (B h_i)_{j-128};  A|B = W1 split.
// 102.4 MB -> L2-resident for the edge pass.
__device__ float g_Y[(size_t)MAX_NODES * NCOL];

// smem (bf16 elements): A_hi[128][136], A_lo[128][136], B_hi[256][136], B_lo[256][136]
#define A_ELEMS (128 * PADK)
#define B_ELEMS (256 * PADK)
#define SMEM_BYTES ((2 * A_ELEMS + 2 * B_ELEMS) * 2)   // 208896 B

static __device__ __forceinline__ uint32_t pack2(float a, float b) {
    uint16_t ua = __bfloat16_as_ushort(__float2bfloat16(a));
    uint16_t ub = __bfloat16_as_ushort(__float2bfloat16(b));
    return (uint32_t)ua | ((uint32_t)ub << 16);
}
static __device__ __forceinline__ float resid(float a) {
    return a - __bfloat162float(__float2bfloat16(a));
}

static __device__ __forceinline__ void hmma(float* d, const uint32_t* a, const uint32_t* b) {
    asm volatile(
        "mma.sync.aligned.m16n8k16.row.col.f32.bf16.bf16.f32 "
        "{%0,%1,%2,%3}, {%4,%5,%6,%7}, {%8,%9}, {%0,%1,%2,%3};"
        : "+f"(d[0]), "+f"(d[1]), "+f"(d[2]), "+f"(d[3])
        : "r"(a[0]), "r"(a[1]), "r"(a[2]), "r"(a[3]), "r"(b[0]), "r"(b[1]));
}

// ---------------------------------------------------------------------------
// K1: Y = H @ G via mma.sync bf16 split (AhBh + AhBl + AlBh, fp32 accum).
// CTA = 128 nodes x 256 cols, K=128. 256 threads = 8 warps.
// Warp tile 64(M) x 32(N), two sequential N-chunks (cols nb, nb+128).
// ---------------------------------------------------------------------------
__global__ __launch_bounds__(256, 1)
void precompute_mma(const float* __restrict__ h,
                    const float* __restrict__ W1,
                    int n_nodes)
{
    extern __shared__ __align__(16) uint16_t smem[];
    uint16_t* Ah = smem;
    uint16_t* Al = Ah + A_ELEMS;
    uint16_t* Bh = Al + A_ELEMS;
    uint16_t* Bl = Bh + B_ELEMS;

    const int tid  = threadIdx.x;
    const int w    = tid >> 5;
    const int lane = tid & 31;
    const int m0   = blockIdx.x * TILE_M;

    // ---- load A (128 x 128 fp32 -> hi/lo bf16) ----
    {
        const float4* h4 = reinterpret_cast<const float4*>(h);
        for (int idx = tid; idx < 128 * 32; idx += 256) {
            const int row = idx >> 5, c4 = idx & 31;
            const int m = m0 + row;
            float4 f = make_float4(0.f, 0.f, 0.f, 0.f);
            if (m < n_nodes) f = h4[(size_t)m * 32 + c4];
            uint2 hi = make_uint2(pack2(f.x, f.y), pack2(f.z, f.w));
            uint2 lo = make_uint2(pack2(resid(f.x), resid(f.y)),
                                  pack2(resid(f.z), resid(f.w)));
            *reinterpret_cast<uint2*>(Ah + row * PADK + c4 * 4) = hi;
            *reinterpret_cast<uint2*>(Al + row * PADK + c4 * 4) = lo;
        }
    }

    // ---- load B: B[n][k] = W1[n%128][ (n>=128?128:0) + k ] ----
    {
        for (int idx = tid; idx < 256 * 32; idx += 256) {
            const int r = idx >> 5, c4 = idx & 31;
            const float4* wr = reinterpret_cast<const float4*>(
                W1 + (size_t)(r & 127) * (2 * HID) + ((r >> 7) * HID));
            float4 f = wr[c4];
            uint2 hi = make_uint2(pack2(f.x, f.y), pack2(f.z, f.w));
            uint2 lo = make_uint2(pack2(resid(f.x), resid(f.y)),
                                  pack2(resid(f.z), resid(f.w)));
            *reinterpret_cast<uint2*>(Bh + r * PADK + c4 * 4) = hi;
            *reinterpret_cast<uint2*>(Bl + r * PADK + c4 * 4) = lo;
        }
    }
    __syncthreads();

    const int g   = lane >> 2;        // group id (row within 8)
    const int tig = lane & 3;         // thread in group
    const int mwarp = (w & 1) * 64;   // warp M base
    const int nbase = (w >> 1) * 32;  // warp N base within a 128-chunk

    #pragma unroll
    for (int cc = 0; cc < 2; cc++) {
        const int nb = nbase + cc * 128;

        float acc[4][4][4];
        #pragma unroll
        for (int mt = 0; mt < 4; mt++)
            #pragma unroll
            for (int nt = 0; nt < 4; nt++)
                #pragma unroll
                for (int r = 0; r < 4; r++) acc[mt][nt][r] = 0.f;

        #pragma unroll
        for (int kb = 0; kb < 8; kb++) {
            const int k0 = kb * 16;

            uint32_t ah[4][4], al[4][4];
            #pragma unroll
            for (int mt = 0; mt < 4; mt++) {
                const int R = mwarp + mt * 16;
                const int o00 = (R + g)     * PADK + k0     + tig * 2;
                const int o10 = (R + g + 8) * PADK + k0     + tig * 2;
                const int o01 = (R + g)     * PADK + k0 + 8 + tig * 2;
                const int o11 = (R + g + 8) * PADK + k0 + 8 + tig * 2;
                ah[mt][0] = *reinterpret_cast<const uint32_t*>(Ah + o00);
                ah[mt][1] = *reinterpret_cast<const uint32_t*>(Ah + o10);
                ah[mt][2] = *reinterpret_cast<const uint32_t*>(Ah + o01);
                ah[mt][3] = *reinterpret_cast<const uint32_t*>(Ah + o11);
                al[mt][0] = *reinterpret_cast<const uint32_t*>(Al + o00);
                al[mt][1] = *reinterpret_cast<const uint32_t*>(Al + o10);
                al[mt][2] = *reinterpret_cast<const uint32_t*>(Al + o01);
                al[mt][3] = *reinterpret_cast<const uint32_t*>(Al + o11);
            }
            uint32_t bh[4][2], bl[4][2];
            #pragma unroll
            for (int nt = 0; nt < 4; nt++) {
                const int C = nb + nt * 8;
                const int o0 = (C + g) * PADK + k0     + tig * 2;
                const int o1 = (C + g) * PADK + k0 + 8 + tig * 2;
                bh[nt][0] = *reinterpret_cast<const uint32_t*>(Bh + o0);
                bh[nt][1] = *reinterpret_cast<const uint32_t*>(Bh + o1);
                bl[nt][0] = *reinterpret_cast<const uint32_t*>(Bl + o0);
                bl[nt][1] = *reinterpret_cast<const uint32_t*>(Bl + o1);
            }

            #pragma unroll
            for (int mt = 0; mt < 4; mt++)
                #pragma unroll
                for (int nt = 0; nt < 4; nt++) {
                    hmma(acc[mt][nt], ah[mt], bh[nt]);   // hi*hi
                    hmma(acc[mt][nt], ah[mt], bl[nt]);   // hi*lo
                    hmma(acc[mt][nt], al[mt], bh[nt]);   // lo*hi
                }
        }

        // ---- store warp tile to g_Y ----
        #pragma unroll
        for (int mt = 0; mt < 4; mt++) {
            const int r0 = m0 + mwarp + mt * 16 + g;
            #pragma unroll
            for (int nt = 0; nt < 4; nt++) {
                const int col = nb + nt * 8 + tig * 2;
                if (r0 < n_nodes)
                    *reinterpret_cast<float2*>(g_Y + (size_t)r0 * NCOL + col) =
                        make_float2(acc[mt][nt][0], acc[mt][nt][1]);
                if (r0 + 8 < n_nodes)
                    *reinterpret_cast<float2*>(g_Y + (size_t)(r0 + 8) * NCOL + col) =
                        make_float2(acc[mt][nt][2], acc[mt][nt][3]);
            }
        }
    }
}

// ---------------------------------------------------------------------------
// K2: one warp per edge (grid-stride). Y is L2-resident.
// ---------------------------------------------------------------------------
__global__ __launch_bounds__(256)
void edge_kernel(const int* __restrict__ src,
                 const int* __restrict__ dst,
                 const float* __restrict__ b1,
                 const float* __restrict__ W2,
                 const float* __restrict__ b2,
                 const float* __restrict__ W3,
                 const float* __restrict__ b3,
                 float* __restrict__ out,
                 int E)
{
    const int lane   = threadIdx.x & 31;
    const int wid    = (blockIdx.x * blockDim.x + threadIdx.x) >> 5;
    const int nwarps = (gridDim.x * blockDim.x) >> 5;

    const float4 b1v = reinterpret_cast<const float4*>(b1)[lane];
    const float4 w2v = reinterpret_cast<const float4*>(W2)[lane];
    const float  c2  = b2[0];
    const float  w3  = W3[0];
    const float  c3  = b3[0];

    const float4* Y4 = reinterpret_cast<const float4*>(g_Y);

    for (int e = wid; e < E; e += nwarps) {
        const int s = src[e];
        const int d = dst[e];

        float4 u = Y4[(size_t)s * 64 + lane];
        float4 v = Y4[(size_t)d * 64 + 32 + lane];

        float x0 = fmaxf(u.x + v.x + b1v.x, 0.f);
        float x1 = fmaxf(u.y + v.y + b1v.y, 0.f);
        float x2 = fmaxf(u.z + v.z + b1v.z, 0.f);
        float x3 = fmaxf(u.w + v.w + b1v.w, 0.f);

        float p = x0 * w2v.x + x1 * w2v.y + x2 * w2v.z + x3 * w2v.w;

        #pragma unroll
        for (int off = 16; off > 0; off >>= 1)
            p += __shfl_xor_sync(0xFFFFFFFFu, p, off);

        if (lane == 0) {
            float s2 = fmaxf(p + c2, 0.f);
            float s3 = fmaxf(fmaf(s2, w3, c3), 0.f);
            out[e] = 1.f / (1.f + expf(-s3));
        }
    }
}

// ---------------------------------------------------------------------------
extern "C" void kernel_launch(void* const* d_in, const int* in_sizes, int n_in,
                              void* d_out, int out_size)
{
    const float* h   = (const float*)d_in[0];
    const int*   src = (const int*)  d_in[1];
    const int*   dst = (const int*)  d_in[2];
    const float* W1  = (const float*)d_in[3];
    const float* b1  = (const float*)d_in[4];
    const float* W2  = (const float*)d_in[5];
    const float* b2  = (const float*)d_in[6];
    const float* W3  = (const float*)d_in[7];
    const float* b3  = (const float*)d_in[8];
    float* out = (float*)d_out;

    const int n_nodes = in_sizes[0] / HID;
    const int E       = in_sizes[1];

    cudaFuncSetAttribute(precompute_mma,
                         cudaFuncAttributeMaxDynamicSharedMemorySize, SMEM_BYTES);

    precompute_mma<<<(n_nodes + TILE_M - 1) / TILE_M, 256, SMEM_BYTES>>>(h, W1, n_nodes);
    edge_kernel<<<4096, 256>>>(src, dst, b1, W2, b2, W3, b3, out, E);
}

// round 4
// speedup vs baseline: 1.9983x; 1.4411x over previous
#include <cuda_runtime.h>
#include <cuda_bf16.h>
#include <math.h>
#include <stdint.h>

#define HID  128
#define NCOL 256
#define MAX_NODES 100000
#define TILE_M 64
#define TILE_N 128
#define PADK 136              // bf16 row stride in smem (272B -> conflict-free)

// Y[i*256 + j] = (j<128) ? (A h_i)_j : (B h_i)_{j-128};  A|B = W1 split.
__device__ float g_Y[(size_t)MAX_NODES * NCOL];

#define A_ELEMS (TILE_M * PADK)     // 8704
#define B_ELEMS (TILE_N * PADK)     // 17408
#define SMEM_BYTES ((2 * A_ELEMS + 2 * B_ELEMS) * 2)   // 104448 B -> 2 CTAs/SM

static __device__ __forceinline__ uint32_t pack2(float a, float b) {
    uint16_t ua = __bfloat16_as_ushort(__float2bfloat16(a));
    uint16_t ub = __bfloat16_as_ushort(__float2bfloat16(b));
    return (uint32_t)ua | ((uint32_t)ub << 16);
}
static __device__ __forceinline__ float resid(float a) {
    return a - __bfloat162float(__float2bfloat16(a));
}
static __device__ __forceinline__ uint32_t smem_u32(const void* p) {
    uint32_t a;
    asm("{ .reg .u64 t; cvta.to.shared.u64 t, %1; cvt.u32.u64 %0, t; }" : "=r"(a) : "l"(p));
    return a;
}

static __device__ __forceinline__ void hmma(float* d, const uint32_t* a, const uint32_t* b) {
    asm volatile(
        "mma.sync.aligned.m16n8k16.row.col.f32.bf16.bf16.f32 "
        "{%0,%1,%2,%3}, {%4,%5,%6,%7}, {%8,%9}, {%0,%1,%2,%3};"
        : "+f"(d[0]), "+f"(d[1]), "+f"(d[2]), "+f"(d[3])
        : "r"(a[0]), "r"(a[1]), "r"(a[2]), "r"(a[3]), "r"(b[0]), "r"(b[1]));
}

#define LDM_X4(r0, r1, r2, r3, addr) \
    asm volatile("ldmatrix.sync.aligned.m8n8.x4.shared.b16 {%0,%1,%2,%3}, [%4];" \
                 : "=r"(r0), "=r"(r1), "=r"(r2), "=r"(r3) : "r"(addr))

// ---------------------------------------------------------------------------
// K1: Y = H @ G via mma.sync bf16 split (AhBh + AhBl + AlBh, fp32 accum).
// CTA = 64 nodes x 128 cols (blockIdx.y picks W1 half), K=128. 8 warps.
// Warp tile 32x32. Fragments via ldmatrix.x4. 2 CTAs/SM.
// ---------------------------------------------------------------------------
__global__ __launch_bounds__(256, 2)
void precompute_mma(const float* __restrict__ h,
                    const float* __restrict__ W1,
                    int n_nodes)
{
    extern __shared__ __align__(16) uint16_t smem[];
    uint16_t* Ah = smem;
    uint16_t* Al = Ah + A_ELEMS;
    uint16_t* Bh = Al + A_ELEMS;
    uint16_t* Bl = Bh + B_ELEMS;

    const int tid  = threadIdx.x;
    const int w    = tid >> 5;
    const int lane = tid & 31;
    const int m0   = blockIdx.x * TILE_M;
    const int half = blockIdx.y;          // 0: u-part, 1: v-part
    const int ybase = half * HID;

    // ---- load A (64 x 128 fp32 -> hi/lo bf16): 2048 float4, 8/thread ----
    {
        const float4* h4 = reinterpret_cast<const float4*>(h);
        #pragma unroll
        for (int idx = tid; idx < TILE_M * 32; idx += 256) {
            const int row = idx >> 5, c4 = idx & 31;
            const int m = m0 + row;
            float4 f = make_float4(0.f, 0.f, 0.f, 0.f);
            if (m < n_nodes) f = h4[(size_t)m * 32 + c4];
            uint2 hi = make_uint2(pack2(f.x, f.y), pack2(f.z, f.w));
            uint2 lo = make_uint2(pack2(resid(f.x), resid(f.y)),
                                  pack2(resid(f.z), resid(f.w)));
            *reinterpret_cast<uint2*>(Ah + row * PADK + c4 * 4) = hi;
            *reinterpret_cast<uint2*>(Al + row * PADK + c4 * 4) = lo;
        }
    }

    // ---- load B: B[n][k] = W1[n][half*128 + k], n in 0..127 ----
    {
        #pragma unroll
        for (int idx = tid; idx < TILE_N * 32; idx += 256) {
            const int r = idx >> 5, c4 = idx & 31;
            const float4* wr = reinterpret_cast<const float4*>(
                W1 + (size_t)r * (2 * HID) + ybase);
            float4 f = wr[c4];
            uint2 hi = make_uint2(pack2(f.x, f.y), pack2(f.z, f.w));
            uint2 lo = make_uint2(pack2(resid(f.x), resid(f.y)),
                                  pack2(resid(f.z), resid(f.w)));
            *reinterpret_cast<uint2*>(Bh + r * PADK + c4 * 4) = hi;
            *reinterpret_cast<uint2*>(Bl + r * PADK + c4 * 4) = lo;
        }
    }
    __syncthreads();

    const int g   = lane >> 2;
    const int tig = lane & 3;
    const int mwarp = (w & 1) * 32;       // warp M base (2 warps in M)
    const int nwarp = (w >> 1) * 32;      // warp N base (4 warps in N)

    // ldmatrix lane base addresses (element index; k advances by +16/step)
    // A: mat0 rows R..R+7 k0-7 | mat1 rows R+8..15 k0-7 | mat2/3 same rows k8-15
    uint32_t a_addr[2][2], b_addr[2][2];  // [mt][hi/lo], [pair][hi/lo]
    {
        const uint32_t sAh = smem_u32(Ah), sAl = smem_u32(Al);
        const uint32_t sBh = smem_u32(Bh), sBl = smem_u32(Bl);
        #pragma unroll
        for (int mt = 0; mt < 2; mt++) {
            const int row = mwarp + mt * 16 + (lane & 15);
            const uint32_t eo = (uint32_t)(row * PADK + ((lane >> 4) & 1) * 8) * 2;
            a_addr[mt][0] = sAh + eo;
            a_addr[mt][1] = sAl + eo;
        }
        #pragma unroll
        for (int p = 0; p < 2; p++) {
            const int rn = nwarp + p * 16 + (lane & 7) + ((lane >> 4) & 1) * 8;
            const uint32_t eo = (uint32_t)(rn * PADK + ((lane >> 3) & 1) * 8) * 2;
            b_addr[p][0] = sBh + eo;
            b_addr[p][1] = sBl + eo;
        }
    }

    float acc[2][4][4];
    #pragma unroll
    for (int mt = 0; mt < 2; mt++)
        #pragma unroll
        for (int nt = 0; nt < 4; nt++)
            #pragma unroll
            for (int r = 0; r < 4; r++) acc[mt][nt][r] = 0.f;

    #pragma unroll
    for (int kb = 0; kb < 8; kb++) {
        const uint32_t ko = (uint32_t)kb * 32;   // 16 elems * 2B

        uint32_t ah[2][4], al[2][4];
        #pragma unroll
        for (int mt = 0; mt < 2; mt++) {
            LDM_X4(ah[mt][0], ah[mt][1], ah[mt][2], ah[mt][3], a_addr[mt][0] + ko);
            LDM_X4(al[mt][0], al[mt][1], al[mt][2], al[mt][3], a_addr[mt][1] + ko);
        }
        uint32_t bh[4][2], bl[4][2];
        #pragma unroll
        for (int p = 0; p < 2; p++) {
            LDM_X4(bh[2*p][0], bh[2*p][1], bh[2*p+1][0], bh[2*p+1][1], b_addr[p][0] + ko);
            LDM_X4(bl[2*p][0], bl[2*p][1], bl[2*p+1][0], bl[2*p+1][1], b_addr[p][1] + ko);
        }

        #pragma unroll
        for (int mt = 0; mt < 2; mt++)
            #pragma unroll
            for (int nt = 0; nt < 4; nt++) {
                hmma(acc[mt][nt], ah[mt], bh[nt]);   // hi*hi
                hmma(acc[mt][nt], ah[mt], bl[nt]);   // hi*lo
                hmma(acc[mt][nt], al[mt], bh[nt]);   // lo*hi
            }
    }

    // ---- store warp tile to g_Y ----
    #pragma unroll
    for (int mt = 0; mt < 2; mt++) {
        const int r0 = m0 + mwarp + mt * 16 + g;
        #pragma unroll
        for (int nt = 0; nt < 4; nt++) {
            const int col = ybase + nwarp + nt * 8 + tig * 2;
            if (r0 < n_nodes)
                *reinterpret_cast<float2*>(g_Y + (size_t)r0 * NCOL + col) =
                    make_float2(acc[mt][nt][0], acc[mt][nt][1]);
            if (r0 + 8 < n_nodes)
                *reinterpret_cast<float2*>(g_Y + (size_t)(r0 + 8) * NCOL + col) =
                    make_float2(acc[mt][nt][2], acc[mt][nt][3]);
        }
    }
}

// ---------------------------------------------------------------------------
// K2: one warp per 2 edges per iteration (grid-stride). Y is L2-resident.
// ---------------------------------------------------------------------------
__global__ __launch_bounds__(256)
void edge_kernel(const int* __restrict__ src,
                 const int* __restrict__ dst,
                 const float* __restrict__ b1,
                 const float* __restrict__ W2,
                 const float* __restrict__ b2,
                 const float* __restrict__ W3,
                 const float* __restrict__ b3,
                 float* __restrict__ out,
                 int E)
{
    const int lane   = threadIdx.x & 31;
    const int wid    = (blockIdx.x * blockDim.x + threadIdx.x) >> 5;
    const int nwarps = (gridDim.x * blockDim.x) >> 5;

    const float4 b1v = reinterpret_cast<const float4*>(b1)[lane];
    const float4 w2v = reinterpret_cast<const float4*>(W2)[lane];
    const float  c2  = b2[0];
    const float  w3  = W3[0];
    const float  c3  = b3[0];

    const float4* Y4 = reinterpret_cast<const float4*>(g_Y);

    for (int e = wid * 2; e < E; e += nwarps * 2) {
        const int e1 = (e + 1 < E) ? (e + 1) : e;
        const int s0 = src[e],  d0 = dst[e];
        const int s1 = src[e1], d1 = dst[e1];

        float4 u0 = Y4[(size_t)s0 * 64 + lane];
        float4 v0 = Y4[(size_t)d0 * 64 + 32 + lane];
        float4 u1 = Y4[(size_t)s1 * 64 + lane];
        float4 v1 = Y4[(size_t)d1 * 64 + 32 + lane];

        float p0, p1;
        {
            float x0 = fmaxf(u0.x + v0.x + b1v.x, 0.f);
            float x1 = fmaxf(u0.y + v0.y + b1v.y, 0.f);
            float x2 = fmaxf(u0.z + v0.z + b1v.z, 0.f);
            float x3 = fmaxf(u0.w + v0.w + b1v.w, 0.f);
            p0 = x0 * w2v.x + x1 * w2v.y + x2 * w2v.z + x3 * w2v.w;
        }
        {
            float x0 = fmaxf(u1.x + v1.x + b1v.x, 0.f);
            float x1 = fmaxf(u1.y + v1.y + b1v.y, 0.f);
            float x2 = fmaxf(u1.z + v1.z + b1v.z, 0.f);
            float x3 = fmaxf(u1.w + v1.w + b1v.w, 0.f);
            p1 = x0 * w2v.x + x1 * w2v.y + x2 * w2v.z + x3 * w2v.w;
        }

        #pragma unroll
        for (int off = 16; off > 0; off >>= 1) {
            p0 += __shfl_xor_sync(0xFFFFFFFFu, p0, off);
            p1 += __shfl_xor_sync(0xFFFFFFFFu, p1, off);
        }

        if (lane == 0) {
            float a2 = fmaxf(p0 + c2, 0.f);
            float a3 = fmaxf(fmaf(a2, w3, c3), 0.f);
            out[e] = 1.f / (1.f + expf(-a3));
            float q2 = fmaxf(p1 + c2, 0.f);
            float q3 = fmaxf(fmaf(q2, w3, c3), 0.f);
            out[e1] = 1.f / (1.f + expf(-q3));
        }
    }
}

// ---------------------------------------------------------------------------
extern "C" void kernel_launch(void* const* d_in, const int* in_sizes, int n_in,
                              void* d_out, int out_size)
{
    const float* h   = (const float*)d_in[0];
    const int*   src = (const int*)  d_in[1];
    const int*   dst = (const int*)  d_in[2];
    const float* W1  = (const float*)d_in[3];
    const float* b1  = (const float*)d_in[4];
    const float* W2  = (const float*)d_in[5];
    const float* b2  = (const float*)d_in[6];
    const float* W3  = (const float*)d_in[7];
    const float* b3  = (const float*)d_in[8];
    float* out = (float*)d_out;

    const int n_nodes = in_sizes[0] / HID;
    const int E       = in_sizes[1];

    cudaFuncSetAttribute(precompute_mma,
                         cudaFuncAttributeMaxDynamicSharedMemorySize, SMEM_BYTES);

    dim3 grid((n_nodes + TILE_M - 1) / TILE_M, 2);
    precompute_mma<<<grid, 256, SMEM_BYTES>>>(h, W1, n_nodes);
    edge_kernel<<<4096, 256>>>(src, dst, b1, W2, b2, W3, b3, out, E);
}

// round 6
// speedup vs baseline: 2.8640x; 1.4332x over previous
#include <cuda_runtime.h>
#include <cuda_fp16.h>
#include <math.h>
#include <stdint.h>

#define HID  128
#define NCOL 256
#define MAX_NODES 100000
#define TILE_M 64
#define PADK 136              // fp16 row stride in smem (272B -> conflict-free ldmatrix)

// Y[i][j] (fp16): j<128 -> (A h_i)_j ; j>=128 -> (B h_i)_{j-128}.  51.2 MB, L2-resident.
__device__ __half g_Yh[(size_t)MAX_NODES * NCOL];

#define A_ELEMS (TILE_M * PADK)     // 8704 halves
#define B_ELEMS (NCOL * PADK)       // 34816 halves
#define SMEM_BYTES ((A_ELEMS + B_ELEMS) * 2)   // 87040 B -> 2 CTAs/SM

static __device__ __forceinline__ uint32_t packh2(float a, float b) {
    __half2 p = __floats2half2_rn(a, b);
    return *reinterpret_cast<uint32_t*>(&p);
}
static __device__ __forceinline__ uint32_t smem_u32(const void* p) {
    uint32_t a;
    asm("{ .reg .u64 t; cvta.to.shared.u64 t, %1; cvt.u32.u64 %0, t; }" : "=r"(a) : "l"(p));
    return a;
}

static __device__ __forceinline__ void hmma(float* d, const uint32_t* a, const uint32_t* b) {
    asm volatile(
        "mma.sync.aligned.m16n8k16.row.col.f32.f16.f16.f32 "
        "{%0,%1,%2,%3}, {%4,%5,%6,%7}, {%8,%9}, {%0,%1,%2,%3};"
        : "+f"(d[0]), "+f"(d[1]), "+f"(d[2]), "+f"(d[3])
        : "r"(a[0]), "r"(a[1]), "r"(a[2]), "r"(a[3]), "r"(b[0]), "r"(b[1]));
}

#define LDM_X4(r0, r1, r2, r3, addr) \
    asm volatile("ldmatrix.sync.aligned.m8n8.x4.shared.b16 {%0,%1,%2,%3}, [%4];" \
                 : "=r"(r0), "=r"(r1), "=r"(r2), "=r"(r3) : "r"(addr))

// ---------------------------------------------------------------------------
// K1: Y = H @ G, single-pass fp16 HMMA (fp32 accumulate).
// CTA = 64 nodes x 256 cols, K=128. 8 warps, warp tile 32(M) x 64(N).
// ---------------------------------------------------------------------------
__global__ __launch_bounds__(256, 2)
void precompute_mma(const float* __restrict__ h,
                    const float* __restrict__ W1,
                    int n_nodes)
{
    extern __shared__ __align__(16) uint16_t smem[];
    uint16_t* Ah = smem;
    uint16_t* Bh = Ah + A_ELEMS;

    const int tid  = threadIdx.x;
    const int w    = tid >> 5;
    const int lane = tid & 31;
    const int m0   = blockIdx.x * TILE_M;

    // ---- A: 64 x 128 fp32 -> fp16 (2048 float4, 8/thread) ----
    {
        const float4* h4 = reinterpret_cast<const float4*>(h);
        #pragma unroll
        for (int idx = tid; idx < TILE_M * 32; idx += 256) {
            const int row = idx >> 5, c4 = idx & 31;
            const int m = m0 + row;
            float4 f = make_float4(0.f, 0.f, 0.f, 0.f);
            if (m < n_nodes) f = h4[(size_t)m * 32 + c4];
            *reinterpret_cast<uint2*>(Ah + row * PADK + c4 * 4) =
                make_uint2(packh2(f.x, f.y), packh2(f.z, f.w));
        }
    }

    // ---- B: row n -> W1[n&127][ (n>>7)*128 + k ] (8192 float4, 32/thread) ----
    {
        #pragma unroll
        for (int idx = tid; idx < NCOL * 32; idx += 256) {
            const int r = idx >> 5, c4 = idx & 31;
            const float4* wr = reinterpret_cast<const float4*>(
                W1 + (size_t)(r & 127) * (2 * HID) + ((r >> 7) * HID));
            float4 f = wr[c4];
            *reinterpret_cast<uint2*>(Bh + r * PADK + c4 * 4) =
                make_uint2(packh2(f.x, f.y), packh2(f.z, f.w));
        }
    }
    __syncthreads();

    const int g   = lane >> 2;
    const int tig = lane & 3;
    const int mwarp = (w & 1) * 32;       // 2 warps in M
    const int nwarp = (w >> 1) * 64;      // 4 warps in N (64 cols each)

    uint32_t a_addr[2], b_addr[4];
    {
        const uint32_t sA = smem_u32(Ah), sB = smem_u32(Bh);
        #pragma unroll
        for (int mt = 0; mt < 2; mt++) {
            const int row = mwarp + mt * 16 + (lane & 15);
            a_addr[mt] = sA + (uint32_t)(row * PADK + ((lane >> 4) & 1) * 8) * 2;
        }
        #pragma unroll
        for (int p = 0; p < 4; p++) {
            const int rn = nwarp + p * 16 + (lane & 7) + ((lane >> 4) & 1) * 8;
            b_addr[p] = sB + (uint32_t)(rn * PADK + ((lane >> 3) & 1) * 8) * 2;
        }
    }

    float acc[2][8][4];
    #pragma unroll
    for (int mt = 0; mt < 2; mt++)
        #pragma unroll
        for (int nt = 0; nt < 8; nt++)
            #pragma unroll
            for (int r = 0; r < 4; r++) acc[mt][nt][r] = 0.f;

    #pragma unroll
    for (int kb = 0; kb < 8; kb++) {
        const uint32_t ko = (uint32_t)kb * 32;   // 16 elems * 2B

        uint32_t ah[2][4];
        #pragma unroll
        for (int mt = 0; mt < 2; mt++)
            LDM_X4(ah[mt][0], ah[mt][1], ah[mt][2], ah[mt][3], a_addr[mt] + ko);

        uint32_t bh[8][2];
        #pragma unroll
        for (int p = 0; p < 4; p++)
            LDM_X4(bh[2*p][0], bh[2*p][1], bh[2*p+1][0], bh[2*p+1][1], b_addr[p] + ko);

        #pragma unroll
        for (int mt = 0; mt < 2; mt++)
            #pragma unroll
            for (int nt = 0; nt < 8; nt++)
                hmma(acc[mt][nt], ah[mt], bh[nt]);
    }

    // ---- store warp tile to g_Yh (fp16) ----
    #pragma unroll
    for (int mt = 0; mt < 2; mt++) {
        const int r0 = m0 + mwarp + mt * 16 + g;
        #pragma unroll
        for (int nt = 0; nt < 8; nt++) {
            const int col = nwarp + nt * 8 + tig * 2;
            if (r0 < n_nodes) {
                __half2 v = __floats2half2_rn(acc[mt][nt][0], acc[mt][nt][1]);
                *reinterpret_cast<__half2*>(g_Yh + (size_t)r0 * NCOL + col) = v;
            }
            if (r0 + 8 < n_nodes) {
                __half2 v = __floats2half2_rn(acc[mt][nt][2], acc[mt][nt][3]);
                *reinterpret_cast<__half2*>(g_Yh + (size_t)(r0 + 8) * NCOL + col) = v;
            }
        }
    }
}

// ---------------------------------------------------------------------------
// K2: one warp per 2 edges per iteration. Y (fp16) is L2-resident.
// ---------------------------------------------------------------------------
__global__ __launch_bounds__(256)
void edge_kernel(const int* __restrict__ src,
                 const int* __restrict__ dst,
                 const float* __restrict__ b1,
                 const float* __restrict__ W2,
                 const float* __restrict__ b2,
                 const float* __restrict__ W3,
                 const float* __restrict__ b3,
                 float* __restrict__ out,
                 int E)
{
    const int lane   = threadIdx.x & 31;
    const int wid    = (blockIdx.x * blockDim.x + threadIdx.x) >> 5;
    const int nwarps = (gridDim.x * blockDim.x) >> 5;

    const float4 b1v = reinterpret_cast<const float4*>(b1)[lane];
    const float4 w2v = reinterpret_cast<const float4*>(W2)[lane];
    const float  c2  = b2[0];
    const float  w3  = W3[0];
    const float  c3  = b3[0];

    const __half* Yh = g_Yh;

    for (int e = wid * 2; e < E; e += nwarps * 2) {
        const int e1 = (e + 1 < E) ? (e + 1) : e;
        const int s0 = src[e],  d0 = dst[e];
        const int s1 = src[e1], d1 = dst[e1];

        uint2 ru0 = *reinterpret_cast<const uint2*>(Yh + (size_t)s0 * NCOL + lane * 4);
        uint2 rv0 = *reinterpret_cast<const uint2*>(Yh + (size_t)d0 * NCOL + HID + lane * 4);
        uint2 ru1 = *reinterpret_cast<const uint2*>(Yh + (size_t)s1 * NCOL + lane * 4);
        uint2 rv1 = *reinterpret_cast<const uint2*>(Yh + (size_t)d1 * NCOL + HID + lane * 4);

        float2 u0a = __half22float2(*reinterpret_cast<__half2*>(&ru0.x));
        float2 u0b = __half22float2(*reinterpret_cast<__half2*>(&ru0.y));
        float2 v0a = __half22float2(*reinterpret_cast<__half2*>(&rv0.x));
        float2 v0b = __half22float2(*reinterpret_cast<__half2*>(&rv0.y));
        float2 u1a = __half22float2(*reinterpret_cast<__half2*>(&ru1.x));
        float2 u1b = __half22float2(*reinterpret_cast<__half2*>(&ru1.y));
        float2 v1a = __half22float2(*reinterpret_cast<__half2*>(&rv1.x));
        float2 v1b = __half22float2(*reinterpret_cast<__half2*>(&rv1.y));

        float p0, p1;
        {
            float x0 = fmaxf(u0a.x + v0a.x + b1v.x, 0.f);
            float x1 = fmaxf(u0a.y + v0a.y + b1v.y, 0.f);
            float x2 = fmaxf(u0b.x + v0b.x + b1v.z, 0.f);
            float x3 = fmaxf(u0b.y + v0b.y + b1v.w, 0.f);
            p0 = x0 * w2v.x + x1 * w2v.y + x2 * w2v.z + x3 * w2v.w;
        }
        {
            float x0 = fmaxf(u1a.x + v1a.x + b1v.x, 0.f);
            float x1 = fmaxf(u1a.y + v1a.y + b1v.y, 0.f);
            float x2 = fmaxf(u1b.x + v1b.x + b1v.z, 0.f);
            float x3 = fmaxf(u1b.y + v1b.y + b1v.w, 0.f);
            p1 = x0 * w2v.x + x1 * w2v.y + x2 * w2v.z + x3 * w2v.w;
        }

        #pragma unroll
        for (int off = 16; off > 0; off >>= 1) {
            p0 += __shfl_xor_sync(0xFFFFFFFFu, p0, off);
            p1 += __shfl_xor_sync(0xFFFFFFFFu, p1, off);
        }

        if (lane == 0) {
            float a2 = fmaxf(p0 + c2, 0.f);
            float a3 = fmaxf(fmaf(a2, w3, c3), 0.f);
            out[e] = 1.f / (1.f + expf(-a3));
            float q2 = fmaxf(p1 + c2, 0.f);
            float q3 = fmaxf(fmaf(q2, w3, c3), 0.f);
            out[e1] = 1.f / (1.f + expf(-q3));
        }
    }
}

// ---------------------------------------------------------------------------
extern "C" void kernel_launch(void* const* d_in, const int* in_sizes, int n_in,
                              void* d_out, int out_size)
{
    const float* h   = (const float*)d_in[0];
    const int*   src = (const int*)  d_in[1];
    const int*   dst = (const int*)  d_in[2];
    const float* W1  = (const float*)d_in[3];
    const float* b1  = (const float*)d_in[4];
    const float* W2  = (const float*)d_in[5];
    const float* b2  = (const float*)d_in[6];
    const float* W3  = (const float*)d_in[7];
    const float* b3  = (const float*)d_in[8];
    float* out = (float*)d_out;

    const int n_nodes = in_sizes[0] / HID;
    const int E       = in_sizes[1];

    cudaFuncSetAttribute(precompute_mma,
                         cudaFuncAttributeMaxDynamicSharedMemorySize, SMEM_BYTES);

    precompute_mma<<<(n_nodes + TILE_M - 1) / TILE_M, 256, SMEM_BYTES>>>(h, W1, n_nodes);
    edge_kernel<<<4096, 256>>>(src, dst, b1, W2, b2, W3, b3, out, E);
}

// round 7
// speedup vs baseline: 3.4002x; 1.1872x over previous
#include <cuda_runtime.h>
#include <cuda_fp16.h>
#include <math.h>
#include <stdint.h>

#define HID  128
#define NCOL 256
#define MAX_NODES 100000
#define TILE_M 64            // per rep
#define REPS   2             // M per CTA = 128
#define PADK 136             // fp16 row stride in smem (272B -> conflict-free ldmatrix)

// Y[i][j] (fp16): j<128 -> (A h_i)_j + b1_j/2 ; j>=128 -> (B h_i)_{j-128} + b1_{j-128}/2
__device__ __half g_Yh[(size_t)MAX_NODES * NCOL];

#define A_ELEMS (TILE_M * PADK)
#define B_ELEMS (NCOL * PADK)
#define SMEM_BYTES ((A_ELEMS + B_ELEMS) * 2)   // 87040 B -> 2 CTAs/SM

static __device__ __forceinline__ uint32_t packh2(float a, float b) {
    __half2 p = __floats2half2_rn(a, b);
    return *reinterpret_cast<uint32_t*>(&p);
}
static __device__ __forceinline__ uint32_t smem_u32(const void* p) {
    uint32_t a;
    asm("{ .reg .u64 t; cvta.to.shared.u64 t, %1; cvt.u32.u64 %0, t; }" : "=r"(a) : "l"(p));
    return a;
}
static __device__ __forceinline__ void hmma(float* d, const uint32_t* a, const uint32_t* b) {
    asm volatile(
        "mma.sync.aligned.m16n8k16.row.col.f32.f16.f16.f32 "
        "{%0,%1,%2,%3}, {%4,%5,%6,%7}, {%8,%9}, {%0,%1,%2,%3};"
        : "+f"(d[0]), "+f"(d[1]), "+f"(d[2]), "+f"(d[3])
        : "r"(a[0]), "r"(a[1]), "r"(a[2]), "r"(a[3]), "r"(b[0]), "r"(b[1]));
}
#define LDM_X4(r0, r1, r2, r3, addr) \
    asm volatile("ldmatrix.sync.aligned.m8n8.x4.shared.b16 {%0,%1,%2,%3}, [%4];" \
                 : "=r"(r0), "=r"(r1), "=r"(r2), "=r"(r3) : "r"(addr))

// ---------------------------------------------------------------------------
// K1: Y = H @ G (fp16 HMMA, fp32 accum), bias/2 folded into epilogue.
// CTA covers 128 nodes (2 reps of 64) x 256 cols; B (W1) loaded once per CTA.
// ---------------------------------------------------------------------------
__global__ __launch_bounds__(256, 2)
void precompute_mma(const float* __restrict__ h,
                    const float* __restrict__ W1,
                    const float* __restrict__ b1,
                    int n_nodes)
{
    extern __shared__ __align__(16) uint16_t smem[];
    uint16_t* Ah = smem;
    uint16_t* Bh = Ah + A_ELEMS;

    const int tid  = threadIdx.x;
    const int w    = tid >> 5;
    const int lane = tid & 31;

    // ---- B: row n -> W1[n&127][ (n>>7)*128 + k ]  (once per CTA) ----
    {
        #pragma unroll
        for (int idx = tid; idx < NCOL * 32; idx += 256) {
            const int r = idx >> 5, c4 = idx & 31;
            const float4* wr = reinterpret_cast<const float4*>(
                W1 + (size_t)(r & 127) * (2 * HID) + ((r >> 7) * HID));
            float4 f = wr[c4];
            *reinterpret_cast<uint2*>(Bh + r * PADK + c4 * 4) =
                make_uint2(packh2(f.x, f.y), packh2(f.z, f.w));
        }
    }

    const int g   = lane >> 2;
    const int tig = lane & 3;
    const int mwarp = (w & 1) * 32;
    const int nwarp = (w >> 1) * 64;

    uint32_t a_addr[2], b_addr[4];
    {
        const uint32_t sA = smem_u32(Ah), sB = smem_u32(Bh);
        #pragma unroll
        for (int mt = 0; mt < 2; mt++) {
            const int row = mwarp + mt * 16 + (lane & 15);
            a_addr[mt] = sA + (uint32_t)(row * PADK + ((lane >> 4) & 1) * 8) * 2;
        }
        #pragma unroll
        for (int p = 0; p < 4; p++) {
            const int rn = nwarp + p * 16 + (lane & 7) + ((lane >> 4) & 1) * 8;
            b_addr[p] = sB + (uint32_t)(rn * PADK + ((lane >> 3) & 1) * 8) * 2;
        }
    }

    #pragma unroll
    for (int rep = 0; rep < REPS; rep++) {
        const int m0 = blockIdx.x * (TILE_M * REPS) + rep * TILE_M;

        // ---- A: 64 x 128 fp32 -> fp16 ----
        {
            const float4* h4 = reinterpret_cast<const float4*>(h);
            #pragma unroll
            for (int idx = tid; idx < TILE_M * 32; idx += 256) {
                const int row = idx >> 5, c4 = idx & 31;
                const int m = m0 + row;
                float4 f = make_float4(0.f, 0.f, 0.f, 0.f);
                if (m < n_nodes) f = h4[(size_t)m * 32 + c4];
                *reinterpret_cast<uint2*>(Ah + row * PADK + c4 * 4) =
                    make_uint2(packh2(f.x, f.y), packh2(f.z, f.w));
            }
        }
        __syncthreads();

        float acc[2][8][4];
        #pragma unroll
        for (int mt = 0; mt < 2; mt++)
            #pragma unroll
            for (int nt = 0; nt < 8; nt++)
                #pragma unroll
                for (int r = 0; r < 4; r++) acc[mt][nt][r] = 0.f;

        #pragma unroll
        for (int kb = 0; kb < 8; kb++) {
            const uint32_t ko = (uint32_t)kb * 32;
            uint32_t ah[2][4];
            #pragma unroll
            for (int mt = 0; mt < 2; mt++)
                LDM_X4(ah[mt][0], ah[mt][1], ah[mt][2], ah[mt][3], a_addr[mt] + ko);
            uint32_t bh[8][2];
            #pragma unroll
            for (int p = 0; p < 4; p++)
                LDM_X4(bh[2*p][0], bh[2*p][1], bh[2*p+1][0], bh[2*p+1][1], b_addr[p] + ko);
            #pragma unroll
            for (int mt = 0; mt < 2; mt++)
                #pragma unroll
                for (int nt = 0; nt < 8; nt++)
                    hmma(acc[mt][nt], ah[mt], bh[nt]);
        }

        // ---- epilogue: += b1/2, store fp16 ----
        #pragma unroll
        for (int mt = 0; mt < 2; mt++) {
            const int r0 = m0 + mwarp + mt * 16 + g;
            #pragma unroll
            for (int nt = 0; nt < 8; nt++) {
                const int col  = nwarp + nt * 8 + tig * 2;
                const int bcol = col & (HID - 1);
                const float bx = b1[bcol] * 0.5f;
                const float by = b1[bcol + 1] * 0.5f;
                if (r0 < n_nodes) {
                    __half2 v = __floats2half2_rn(acc[mt][nt][0] + bx, acc[mt][nt][1] + by);
                    *reinterpret_cast<__half2*>(g_Yh + (size_t)r0 * NCOL + col) = v;
                }
                if (r0 + 8 < n_nodes) {
                    __half2 v = __floats2half2_rn(acc[mt][nt][2] + bx, acc[mt][nt][3] + by);
                    *reinterpret_cast<__half2*>(g_Yh + (size_t)(r0 + 8) * NCOL + col) = v;
                }
            }
        }
        __syncthreads();   // protect A before next rep overwrites
    }
}

// ---------------------------------------------------------------------------
// K2: 8 lanes per edge, 4 edges per warp-iteration, half2 math.
// p = sum_j w2_j * relu(u'[s]_j + v'[d]_j)   (b1 already folded into Y)
// ---------------------------------------------------------------------------
__global__ __launch_bounds__(256)
void edge_kernel(const int* __restrict__ src,
                 const int* __restrict__ dst,
                 const float* __restrict__ W2,
                 const float* __restrict__ b2,
                 const float* __restrict__ W3,
                 const float* __restrict__ b3,
                 float* __restrict__ out,
                 int E)
{
    const int lane = threadIdx.x & 31;
    const int sub  = lane >> 3;        // which of 4 edges in this warp
    const int l8   = lane & 7;         // lane within edge group
    const int wid  = (blockIdx.x * blockDim.x + threadIdx.x) >> 5;
    const int nwarps = (gridDim.x * blockDim.x) >> 5;

    // per-lane W2 slice: features l8*16 .. l8*16+15 -> 8 half2
    __half2 w2h[8];
    {
        const float4* W2_4 = reinterpret_cast<const float4*>(W2);
        #pragma unroll
        for (int i = 0; i < 4; i++) {
            float4 q = W2_4[l8 * 4 + i];
            w2h[2*i]   = __floats2half2_rn(q.x, q.y);
            w2h[2*i+1] = __floats2half2_rn(q.z, q.w);
        }
    }
    const float c2 = b2[0];
    const float w3 = W3[0];
    const float c3 = b3[0];
    const __half2 zero2 = __floats2half2_rn(0.f, 0.f);

    for (int e = wid * 4 + sub; ; e += nwarps * 4) {
        // all lanes of the warp agree on whether any sub is in range
        const int ebase = e - sub;
        if (ebase >= E) break;
        const int ec = (e < E) ? e : (E - 1);

        const int s = src[ec];
        const int d = dst[ec];

        const uint32_t uo = (uint32_t)s * NCOL + l8 * 16;
        const uint32_t vo = (uint32_t)d * NCOL + HID + l8 * 16;
        const uint4* up = reinterpret_cast<const uint4*>(g_Yh + uo);
        const uint4* vp = reinterpret_cast<const uint4*>(g_Yh + vo);
        uint4 ua = up[0], ub = up[1];
        uint4 va = vp[0], vb = vp[1];

        const __half2* uh = reinterpret_cast<const __half2*>(&ua);   // 4 half2
        const __half2* uH = reinterpret_cast<const __half2*>(&ub);
        const __half2* vh = reinterpret_cast<const __half2*>(&va);
        const __half2* vH = reinterpret_cast<const __half2*>(&vb);

        __half2 pr[8];
        #pragma unroll
        for (int i = 0; i < 4; i++) {
            __half2 x = __hmax2(__hadd2(uh[i], vh[i]), zero2);
            pr[i] = __hmul2(x, w2h[i]);
        }
        #pragma unroll
        for (int i = 0; i < 4; i++) {
            __half2 x = __hmax2(__hadd2(uH[i], vH[i]), zero2);
            pr[4 + i] = __hmul2(x, w2h[4 + i]);
        }

        __half2 c0 = __hadd2(__hadd2(pr[0], pr[1]), __hadd2(pr[2], pr[3]));
        __half2 c1 = __hadd2(__hadd2(pr[4], pr[5]), __hadd2(pr[6], pr[7]));
        float2 f0 = __half22float2(c0);
        float2 f1 = __half22float2(c1);
        float p = (f0.x + f0.y) + (f1.x + f1.y);

        p += __shfl_xor_sync(0xFFFFFFFFu, p, 1);
        p += __shfl_xor_sync(0xFFFFFFFFu, p, 2);
        p += __shfl_xor_sync(0xFFFFFFFFu, p, 4);

        if (l8 == 0 && e < E) {
            float s2 = fmaxf(p + c2, 0.f);
            float s3 = fmaxf(fmaf(s2, w3, c3), 0.f);
            out[e] = __fdividef(1.f, 1.f + __expf(-s3));
        }
    }
}

// ---------------------------------------------------------------------------
extern "C" void kernel_launch(void* const* d_in, const int* in_sizes, int n_in,
                              void* d_out, int out_size)
{
    const float* h   = (const float*)d_in[0];
    const int*   src = (const int*)  d_in[1];
    const int*   dst = (const int*)  d_in[2];
    const float* W1  = (const float*)d_in[3];
    const float* b1  = (const float*)d_in[4];
    const float* W2  = (const float*)d_in[5];
    const float* b2  = (const float*)d_in[6];
    const float* W3  = (const float*)d_in[7];
    const float* b3  = (const float*)d_in[8];
    float* out = (float*)d_out;

    const int n_nodes = in_sizes[0] / HID;
    const int E       = in_sizes[1];

    cudaFuncSetAttribute(precompute_mma,
                         cudaFuncAttributeMaxDynamicSharedMemorySize, SMEM_BYTES);

    precompute_mma<<<(n_nodes + TILE_M * REPS - 1) / (TILE_M * REPS), 256, SMEM_BYTES>>>(
        h, W1, b1, n_nodes);
    edge_kernel<<<4096, 256>>>(src, dst, W2, b2, W3, b3, out, E);
}

// round 8
// speedup vs baseline: 4.2336x; 1.2451x over previous
#include <cuda_runtime.h>
#include <cuda_fp16.h>
#include <math.h>
#include <stdint.h>

#define HID  128
#define NCOL 256
#define MAX_NODES 100000
#define TILE_M 64
#define PADK 136             // fp16 row stride in smem (272B -> conflict-free ldmatrix)
#define K1_GRID 296

// Y (fp16), 51.2 MB, L2-resident. PERMUTED column layout:
//   physical p = nw*64 + c*32 + tig*8 + nt4*2 + b   (within each 128-col half)
//   logical  j = nw*64 + (c*4+nt4)*8 + tig*2 + b
// b1/2 folded into both halves.
__device__ __half g_Yh[(size_t)MAX_NODES * NCOL];

#define A_ELEMS (TILE_M * PADK)     // 8704 halves
#define B_ELEMS (NCOL * PADK)       // 34816 halves
#define SMEM_BYTES ((A_ELEMS + B_ELEMS) * 2 + 512)   // +b1s -> 87552 B, 2 CTAs/SM

static __device__ __forceinline__ uint32_t packh2(float a, float b) {
    __half2 p = __floats2half2_rn(a, b);
    return *reinterpret_cast<uint32_t*>(&p);
}
static __device__ __forceinline__ uint32_t smem_u32(const void* p) {
    uint32_t a;
    asm("{ .reg .u64 t; cvta.to.shared.u64 t, %1; cvt.u32.u64 %0, t; }" : "=r"(a) : "l"(p));
    return a;
}
static __device__ __forceinline__ void hmma(float* d, const uint32_t* a, const uint32_t* b) {
    asm volatile(
        "mma.sync.aligned.m16n8k16.row.col.f32.f16.f16.f32 "
        "{%0,%1,%2,%3}, {%4,%5,%6,%7}, {%8,%9}, {%0,%1,%2,%3};"
        : "+f"(d[0]), "+f"(d[1]), "+f"(d[2]), "+f"(d[3])
        : "r"(a[0]), "r"(a[1]), "r"(a[2]), "r"(a[3]), "r"(b[0]), "r"(b[1]));
}
#define LDM_X4(r0, r1, r2, r3, addr) \
    asm volatile("ldmatrix.sync.aligned.m8n8.x4.shared.b16 {%0,%1,%2,%3}, [%4];" \
                 : "=r"(r0), "=r"(r1), "=r"(r2), "=r"(r3) : "r"(addr))

// ---------------------------------------------------------------------------
// K1: persistent. Y = H @ G (fp16 HMMA, fp32 accum), coalesced permuted stores.
// ---------------------------------------------------------------------------
__global__ __launch_bounds__(256, 2)
void precompute_mma(const float* __restrict__ h,
                    const float* __restrict__ W1,
                    const float* __restrict__ b1,
                    int n_nodes, int n_tiles)
{
    extern __shared__ __align__(16) uint16_t smem[];
    uint16_t* Ah = smem;
    uint16_t* Bh = Ah + A_ELEMS;
    float*    b1s = reinterpret_cast<float*>(Bh + B_ELEMS);

    const int tid  = threadIdx.x;
    const int w    = tid >> 5;
    const int lane = tid & 31;

    // ---- once per CTA: B (W1 repacked) + b1/2 ----
    #pragma unroll
    for (int idx = tid; idx < NCOL * 32; idx += 256) {
        const int r = idx >> 5, c4 = idx & 31;
        const float4* wr = reinterpret_cast<const float4*>(
            W1 + (size_t)(r & 127) * (2 * HID) + ((r >> 7) * HID));
        float4 f = wr[c4];
        *reinterpret_cast<uint2*>(Bh + r * PADK + c4 * 4) =
            make_uint2(packh2(f.x, f.y), packh2(f.z, f.w));
    }
    if (tid < HID) b1s[tid] = b1[tid] * 0.5f;

    const int g   = lane >> 2;
    const int tig = lane & 3;
    const int mwarp = (w & 1) * 32;
    const int nw    = w >> 1;          // 0..3
    const int nwarp = nw * 64;

    uint32_t a_addr[2], b_addr[4];
    {
        const uint32_t sA = smem_u32(Ah), sB = smem_u32(Bh);
        #pragma unroll
        for (int mt = 0; mt < 2; mt++) {
            const int row = mwarp + mt * 16 + (lane & 15);
            a_addr[mt] = sA + (uint32_t)(row * PADK + ((lane >> 4) & 1) * 8) * 2;
        }
        #pragma unroll
        for (int p = 0; p < 4; p++) {
            const int rn = nwarp + p * 16 + (lane & 7) + ((lane >> 4) & 1) * 8;
            b_addr[p] = sB + (uint32_t)(rn * PADK + ((lane >> 3) & 1) * 8) * 2;
        }
    }

    const float4* h4 = reinterpret_cast<const float4*>(h);

    for (int t = blockIdx.x; t < n_tiles; t += gridDim.x) {
        const int m0 = t * TILE_M;

        // ---- A: 64 x 128 fp32 -> fp16 ----
        #pragma unroll
        for (int idx = tid; idx < TILE_M * 32; idx += 256) {
            const int row = idx >> 5, c4 = idx & 31;
            const int m = m0 + row;
            float4 f = make_float4(0.f, 0.f, 0.f, 0.f);
            if (m < n_nodes) f = h4[(size_t)m * 32 + c4];
            *reinterpret_cast<uint2*>(Ah + row * PADK + c4 * 4) =
                make_uint2(packh2(f.x, f.y), packh2(f.z, f.w));
        }
        __syncthreads();

        float acc[2][8][4];
        #pragma unroll
        for (int mt = 0; mt < 2; mt++)
            #pragma unroll
            for (int nt = 0; nt < 8; nt++)
                #pragma unroll
                for (int r = 0; r < 4; r++) acc[mt][nt][r] = 0.f;

        #pragma unroll
        for (int kb = 0; kb < 8; kb++) {
            const uint32_t ko = (uint32_t)kb * 32;
            uint32_t ah[2][4];
            #pragma unroll
            for (int mt = 0; mt < 2; mt++)
                LDM_X4(ah[mt][0], ah[mt][1], ah[mt][2], ah[mt][3], a_addr[mt] + ko);
            uint32_t bh[8][2];
            #pragma unroll
            for (int p = 0; p < 4; p++)
                LDM_X4(bh[2*p][0], bh[2*p][1], bh[2*p+1][0], bh[2*p+1][1], b_addr[p] + ko);
            #pragma unroll
            for (int mt = 0; mt < 2; mt++)
                #pragma unroll
                for (int nt = 0; nt < 8; nt++)
                    hmma(acc[mt][nt], ah[mt], bh[nt]);
        }

        // ---- epilogue: bias fold + PERMUTED coalesced 16B stores ----
        #pragma unroll
        for (int mt = 0; mt < 2; mt++) {
            const int r0 = m0 + mwarp + mt * 16 + g;
            const int r1 = r0 + 8;
            #pragma unroll
            for (int c = 0; c < 2; c++) {
                uint4 s0, s1;
                __half2* h0 = reinterpret_cast<__half2*>(&s0);
                __half2* h1 = reinterpret_cast<__half2*>(&s1);
                #pragma unroll
                for (int q = 0; q < 4; q++) {
                    const int nt = c * 4 + q;
                    const int bcol = (nwarp + nt * 8 + tig * 2) & (HID - 1);
                    const float2 bb = *reinterpret_cast<const float2*>(&b1s[bcol]);
                    h0[q] = __floats2half2_rn(acc[mt][nt][0] + bb.x, acc[mt][nt][1] + bb.y);
                    h1[q] = __floats2half2_rn(acc[mt][nt][2] + bb.x, acc[mt][nt][3] + bb.y);
                }
                const uint32_t off = (uint32_t)nwarp + c * 32 + tig * 8;   // halves
                if (r0 < n_nodes)
                    *reinterpret_cast<uint4*>(g_Yh + (size_t)r0 * NCOL + off) = s0;
                if (r1 < n_nodes)
                    *reinterpret_cast<uint4*>(g_Yh + (size_t)r1 * NCOL + off) = s1;
            }
        }
        __syncthreads();   // Ah reused next tile
    }
}

// ---------------------------------------------------------------------------
// K2: 8 lanes/edge, 8 edges per warp-iteration (2 per sub-group), half2 math.
// W2 is gathered through the inverse Y permutation.
// ---------------------------------------------------------------------------
__global__ __launch_bounds__(256)
void edge_kernel(const int* __restrict__ src,
                 const int* __restrict__ dst,
                 const float* __restrict__ W2,
                 const float* __restrict__ b2,
                 const float* __restrict__ W3,
                 const float* __restrict__ b3,
                 float* __restrict__ out,
                 int E)
{
    const int lane = threadIdx.x & 31;
    const int sub  = lane >> 3;
    const int l8   = lane & 7;
    const int wid  = (blockIdx.x * blockDim.x + threadIdx.x) >> 5;
    const int nwarps = (gridDim.x * blockDim.x) >> 5;

    // per-lane W2 slice via inverse permutation of physical halves p = l8*16 + q
    __half2 w2h[8];
    #pragma unroll
    for (int i = 0; i < 8; i++) {
        const int p   = l8 * 16 + i * 2;
        const int pnw = p >> 6, pc = (p >> 5) & 1, ptig = (p >> 3) & 3, pnt4 = (p >> 1) & 3;
        const int j   = pnw * 64 + (pc * 4 + pnt4) * 8 + ptig * 2;
        w2h[i] = __floats2half2_rn(W2[j], W2[j + 1]);
    }
    const float c2 = b2[0];
    const float w3 = W3[0];
    const float c3 = b3[0];
    const __half2 zero2 = __floats2half2_rn(0.f, 0.f);

    for (int e = wid * 8 + sub; ; e += nwarps * 8) {
        const int ebase = e - sub;
        if (ebase >= E) break;
        const int eA = (e < E) ? e : (E - 1);
        const int e2 = e + 4;
        const int eB = (e2 < E) ? e2 : (E - 1);

        const int sA = src[eA], dA = dst[eA];
        const int sB = src[eB], dB = dst[eB];

        const uint4* upA = reinterpret_cast<const uint4*>(g_Yh + (uint32_t)sA * NCOL + l8 * 16);
        const uint4* vpA = reinterpret_cast<const uint4*>(g_Yh + (uint32_t)dA * NCOL + HID + l8 * 16);
        const uint4* upB = reinterpret_cast<const uint4*>(g_Yh + (uint32_t)sB * NCOL + l8 * 16);
        const uint4* vpB = reinterpret_cast<const uint4*>(g_Yh + (uint32_t)dB * NCOL + HID + l8 * 16);
        uint4 ua0 = upA[0], ua1 = upA[1];
        uint4 va0 = vpA[0], va1 = vpA[1];
        uint4 ub0 = upB[0], ub1 = upB[1];
        uint4 vb0 = vpB[0], vb1 = vpB[1];

        const __half2* uhA0 = reinterpret_cast<const __half2*>(&ua0);
        const __half2* uhA1 = reinterpret_cast<const __half2*>(&ua1);
        const __half2* vhA0 = reinterpret_cast<const __half2*>(&va0);
        const __half2* vhA1 = reinterpret_cast<const __half2*>(&va1);
        const __half2* uhB0 = reinterpret_cast<const __half2*>(&ub0);
        const __half2* uhB1 = reinterpret_cast<const __half2*>(&ub1);
        const __half2* vhB0 = reinterpret_cast<const __half2*>(&vb0);
        const __half2* vhB1 = reinterpret_cast<const __half2*>(&vb1);

        __half2 accA = zero2, accB = zero2;
        #pragma unroll
        for (int i = 0; i < 4; i++) {
            __half2 xA = __hmax2(__hadd2(uhA0[i], vhA0[i]), zero2);
            accA = __hfma2(xA, w2h[i], accA);
            __half2 xB = __hmax2(__hadd2(uhB0[i], vhB0[i]), zero2);
            accB = __hfma2(xB, w2h[i], accB);
        }
        #pragma unroll
        for (int i = 0; i < 4; i++) {
            __half2 xA = __hmax2(__hadd2(uhA1[i], vhA1[i]), zero2);
            accA = __hfma2(xA, w2h[4 + i], accA);
            __half2 xB = __hmax2(__hadd2(uhB1[i], vhB1[i]), zero2);
            accB = __hfma2(xB, w2h[4 + i], accB);
        }

        float2 fA = __half22float2(accA);
        float2 fB = __half22float2(accB);
        float pA = fA.x + fA.y;
        float pB = fB.x + fB.y;

        pA += __shfl_xor_sync(0xFFFFFFFFu, pA, 1);
        pB += __shfl_xor_sync(0xFFFFFFFFu, pB, 1);
        pA += __shfl_xor_sync(0xFFFFFFFFu, pA, 2);
        pB += __shfl_xor_sync(0xFFFFFFFFu, pB, 2);
        pA += __shfl_xor_sync(0xFFFFFFFFu, pA, 4);
        pB += __shfl_xor_sync(0xFFFFFFFFu, pB, 4);

        if (l8 == 0) {
            if (e < E) {
                float s2 = fmaxf(pA + c2, 0.f);
                float s3 = fmaxf(fmaf(s2, w3, c3), 0.f);
                out[e] = __fdividef(1.f, 1.f + __expf(-s3));
            }
            if (e2 < E) {
                float s2 = fmaxf(pB + c2, 0.f);
                float s3 = fmaxf(fmaf(s2, w3, c3), 0.f);
                out[e2] = __fdividef(1.f, 1.f + __expf(-s3));
            }
        }
    }
}

// ---------------------------------------------------------------------------
extern "C" void kernel_launch(void* const* d_in, const int* in_sizes, int n_in,
                              void* d_out, int out_size)
{
    const float* h   = (const float*)d_in[0];
    const int*   src = (const int*)  d_in[1];
    const int*   dst = (const int*)  d_in[2];
    const float* W1  = (const float*)d_in[3];
    const float* b1  = (const float*)d_in[4];
    const float* W2  = (const float*)d_in[5];
    const float* b2  = (const float*)d_in[6];
    const float* W3  = (const float*)d_in[7];
    const float* b3  = (const float*)d_in[8];
    float* out = (float*)d_out;

    const int n_nodes = in_sizes[0] / HID;
    const int E       = in_sizes[1];
    const int n_tiles = (n_nodes + TILE_M - 1) / TILE_M;

    cudaFuncSetAttribute(precompute_mma,
                         cudaFuncAttributeMaxDynamicSharedMemorySize, SMEM_BYTES);

    precompute_mma<<<K1_GRID, 256, SMEM_BYTES>>>(h, W1, b1, n_nodes, n_tiles);
    edge_kernel<<<4096, 256>>>(src, dst, W2, b2, W3, b3, out, E);
}

// round 9
// speedup vs baseline: 4.6347x; 1.0947x over previous
#include <cuda_runtime.h>
#include <cuda_fp16.h>
#include <math.h>
#include <stdint.h>

#define HID  128
#define NCOL 256
#define MAX_NODES 100000
#define TILE_M 64
#define PADK 136             // fp16 row stride in smem (272B -> conflict-free ldmatrix)
#define K1_GRID 296

// Y (fp16), 51.2 MB, L2-resident. PERMUTED column layout (per 128-col half):
//   physical q = qnw*64 + qc*32 + qtig*8 + qnt4*2 + b
//   logical  j = qnw*64 + (qc*4+qnt4)*8 + qtig*2 + b
// b1/2 folded into both halves.
__device__ __half g_Yh[(size_t)MAX_NODES * NCOL];

#define A_ELEMS (TILE_M * PADK)     // 8704 halves
#define B_ELEMS (NCOL * PADK)       // 34816 halves
#define SMEM_BYTES ((A_ELEMS + B_ELEMS) * 2 + 512)   // 87552 B, 2 CTAs/SM

static __device__ __forceinline__ uint32_t packh2(float a, float b) {
    __half2 p = __floats2half2_rn(a, b);
    return *reinterpret_cast<uint32_t*>(&p);
}
static __device__ __forceinline__ uint32_t smem_u32(const void* p) {
    uint32_t a;
    asm("{ .reg .u64 t; cvta.to.shared.u64 t, %1; cvt.u32.u64 %0, t; }" : "=r"(a) : "l"(p));
    return a;
}
static __device__ __forceinline__ void hmma(float* d, const uint32_t* a, const uint32_t* b) {
    asm volatile(
        "mma.sync.aligned.m16n8k16.row.col.f32.f16.f16.f32 "
        "{%0,%1,%2,%3}, {%4,%5,%6,%7}, {%8,%9}, {%0,%1,%2,%3};"
        : "+f"(d[0]), "+f"(d[1]), "+f"(d[2]), "+f"(d[3])
        : "r"(a[0]), "r"(a[1]), "r"(a[2]), "r"(a[3]), "r"(b[0]), "r"(b[1]));
}
#define LDM_X4(r0, r1, r2, r3, addr) \
    asm volatile("ldmatrix.sync.aligned.m8n8.x4.shared.b16 {%0,%1,%2,%3}, [%4];" \
                 : "=r"(r0), "=r"(r1), "=r"(r2), "=r"(r3) : "r"(addr))

// ---------------------------------------------------------------------------
// K1: persistent. Y = H @ G (fp16 HMMA, fp32 accum), coalesced permuted stores.
// (unchanged from round 8)
// ---------------------------------------------------------------------------
__global__ __launch_bounds__(256, 2)
void precompute_mma(const float* __restrict__ h,
                    const float* __restrict__ W1,
                    const float* __restrict__ b1,
                    int n_nodes, int n_tiles)
{
    extern __shared__ __align__(16) uint16_t smem[];
    uint16_t* Ah = smem;
    uint16_t* Bh = Ah + A_ELEMS;
    float*    b1s = reinterpret_cast<float*>(Bh + B_ELEMS);

    const int tid  = threadIdx.x;
    const int w    = tid >> 5;
    const int lane = tid & 31;

    #pragma unroll
    for (int idx = tid; idx < NCOL * 32; idx += 256) {
        const int r = idx >> 5, c4 = idx & 31;
        const float4* wr = reinterpret_cast<const float4*>(
            W1 + (size_t)(r & 127) * (2 * HID) + ((r >> 7) * HID));
        float4 f = wr[c4];
        *reinterpret_cast<uint2*>(Bh + r * PADK + c4 * 4) =
            make_uint2(packh2(f.x, f.y), packh2(f.z, f.w));
    }
    if (tid < HID) b1s[tid] = b1[tid] * 0.5f;

    const int g   = lane >> 2;
    const int tig = lane & 3;
    const int mwarp = (w & 1) * 32;
    const int nw    = w >> 1;
    const int nwarp = nw * 64;

    uint32_t a_addr[2], b_addr[4];
    {
        const uint32_t sA = smem_u32(Ah), sB = smem_u32(Bh);
        #pragma unroll
        for (int mt = 0; mt < 2; mt++) {
            const int row = mwarp + mt * 16 + (lane & 15);
            a_addr[mt] = sA + (uint32_t)(row * PADK + ((lane >> 4) & 1) * 8) * 2;
        }
        #pragma unroll
        for (int p = 0; p < 4; p++) {
            const int rn = nwarp + p * 16 + (lane & 7) + ((lane >> 4) & 1) * 8;
            b_addr[p] = sB + (uint32_t)(rn * PADK + ((lane >> 3) & 1) * 8) * 2;
        }
    }

    const float4* h4 = reinterpret_cast<const float4*>(h);

    for (int t = blockIdx.x; t < n_tiles; t += gridDim.x) {
        const int m0 = t * TILE_M;

        #pragma unroll
        for (int idx = tid; idx < TILE_M * 32; idx += 256) {
            const int row = idx >> 5, c4 = idx & 31;
            const int m = m0 + row;
            float4 f = make_float4(0.f, 0.f, 0.f, 0.f);
            if (m < n_nodes) f = h4[(size_t)m * 32 + c4];
            *reinterpret_cast<uint2*>(Ah + row * PADK + c4 * 4) =
                make_uint2(packh2(f.x, f.y), packh2(f.z, f.w));
        }
        __syncthreads();

        float acc[2][8][4];
        #pragma unroll
        for (int mt = 0; mt < 2; mt++)
            #pragma unroll
            for (int nt = 0; nt < 8; nt++)
                #pragma unroll
                for (int r = 0; r < 4; r++) acc[mt][nt][r] = 0.f;

        #pragma unroll
        for (int kb = 0; kb < 8; kb++) {
            const uint32_t ko = (uint32_t)kb * 32;
            uint32_t ah[2][4];
            #pragma unroll
            for (int mt = 0; mt < 2; mt++)
                LDM_X4(ah[mt][0], ah[mt][1], ah[mt][2], ah[mt][3], a_addr[mt] + ko);
            uint32_t bh[8][2];
            #pragma unroll
            for (int p = 0; p < 4; p++)
                LDM_X4(bh[2*p][0], bh[2*p][1], bh[2*p+1][0], bh[2*p+1][1], b_addr[p] + ko);
            #pragma unroll
            for (int mt = 0; mt < 2; mt++)
                #pragma unroll
                for (int nt = 0; nt < 8; nt++)
                    hmma(acc[mt][nt], ah[mt], bh[nt]);
        }

        #pragma unroll
        for (int mt = 0; mt < 2; mt++) {
            const int r0 = m0 + mwarp + mt * 16 + g;
            const int r1 = r0 + 8;
            #pragma unroll
            for (int c = 0; c < 2; c++) {
                uint4 s0, s1;
                __half2* h0 = reinterpret_cast<__half2*>(&s0);
                __half2* h1 = reinterpret_cast<__half2*>(&s1);
                #pragma unroll
                for (int q = 0; q < 4; q++) {
                    const int nt = c * 4 + q;
                    const int bcol = (nwarp + nt * 8 + tig * 2) & (HID - 1);
                    const float2 bb = *reinterpret_cast<const float2*>(&b1s[bcol]);
                    h0[q] = __floats2half2_rn(acc[mt][nt][0] + bb.x, acc[mt][nt][1] + bb.y);
                    h1[q] = __floats2half2_rn(acc[mt][nt][2] + bb.x, acc[mt][nt][3] + bb.y);
                }
                const uint32_t off = (uint32_t)nwarp + c * 32 + tig * 8;
                if (r0 < n_nodes)
                    *reinterpret_cast<uint4*>(g_Yh + (size_t)r0 * NCOL + off) = s0;
                if (r1 < n_nodes)
                    *reinterpret_cast<uint4*>(g_Yh + (size_t)r1 * NCOL + off) = s1;
            }
        }
        __syncthreads();
    }
}

// ---------------------------------------------------------------------------
// K2: 8 lanes/edge, 8 edges per warp-iteration, half2 math.
// Lane l8 reads halves [l8*8 .. +7] and [64+l8*8 .. +7] of each 128-half:
// every LDG.128 covers one full 128B line per subgroup (min wavefronts).
// W2 gathered through the matching inverse permutation.
// ---------------------------------------------------------------------------
__global__ __launch_bounds__(256)
void edge_kernel(const int* __restrict__ src,
                 const int* __restrict__ dst,
                 const float* __restrict__ W2,
                 const float* __restrict__ b2,
                 const float* __restrict__ W3,
                 const float* __restrict__ b3,
                 float* __restrict__ out,
                 int E)
{
    const int lane = threadIdx.x & 31;
    const int sub  = lane >> 3;
    const int l8   = lane & 7;
    const int wid  = (blockIdx.x * blockDim.x + threadIdx.x) >> 5;
    const int nwarps = (gridDim.x * blockDim.x) >> 5;

    // lane features (physical within-half): i<4 -> q = l8*8 + i*2 ; i>=4 -> q = 64 + l8*8 + (i-4)*2
    __half2 w2h[8];
    #pragma unroll
    for (int i = 0; i < 8; i++) {
        const int q   = (i < 4) ? (l8 * 8 + i * 2) : (64 + l8 * 8 + (i - 4) * 2);
        const int qnw = q >> 6, qc = (q >> 5) & 1, qtig = (q >> 3) & 3, qnt4 = (q >> 1) & 3;
        const int j   = qnw * 64 + (qc * 4 + qnt4) * 8 + qtig * 2;
        w2h[i] = __floats2half2_rn(W2[j], W2[j + 1]);
    }
    const float c2 = b2[0];
    const float w3 = W3[0];
    const float c3 = b3[0];
    const __half2 zero2 = __floats2half2_rn(0.f, 0.f);

    for (int e = wid * 8 + sub; ; e += nwarps * 8) {
        const int ebase = e - sub;
        if (ebase >= E) break;
        const int eA = (e < E) ? e : (E - 1);
        const int e2 = e + 4;
        const int eB = (e2 < E) ? e2 : (E - 1);

        const int sA = src[eA], dA = dst[eA];
        const int sB = src[eB], dB = dst[eB];

        const __half* YA_u = g_Yh + (uint32_t)sA * NCOL;
        const __half* YA_v = g_Yh + (uint32_t)dA * NCOL + HID;
        const __half* YB_u = g_Yh + (uint32_t)sB * NCOL;
        const __half* YB_v = g_Yh + (uint32_t)dB * NCOL + HID;

        uint4 ua0 = *reinterpret_cast<const uint4*>(YA_u + l8 * 8);
        uint4 ua1 = *reinterpret_cast<const uint4*>(YA_u + 64 + l8 * 8);
        uint4 va0 = *reinterpret_cast<const uint4*>(YA_v + l8 * 8);
        uint4 va1 = *reinterpret_cast<const uint4*>(YA_v + 64 + l8 * 8);
        uint4 ub0 = *reinterpret_cast<const uint4*>(YB_u + l8 * 8);
        uint4 ub1 = *reinterpret_cast<const uint4*>(YB_u + 64 + l8 * 8);
        uint4 vb0 = *reinterpret_cast<const uint4*>(YB_v + l8 * 8);
        uint4 vb1 = *reinterpret_cast<const uint4*>(YB_v + 64 + l8 * 8);

        const __half2* uhA0 = reinterpret_cast<const __half2*>(&ua0);
        const __half2* uhA1 = reinterpret_cast<const __half2*>(&ua1);
        const __half2* vhA0 = reinterpret_cast<const __half2*>(&va0);
        const __half2* vhA1 = reinterpret_cast<const __half2*>(&va1);
        const __half2* uhB0 = reinterpret_cast<const __half2*>(&ub0);
        const __half2* uhB1 = reinterpret_cast<const __half2*>(&ub1);
        const __half2* vhB0 = reinterpret_cast<const __half2*>(&vb0);
        const __half2* vhB1 = reinterpret_cast<const __half2*>(&vb1);

        __half2 accA = zero2, accB = zero2;
        #pragma unroll
        for (int i = 0; i < 4; i++) {
            __half2 xA = __hmax2(__hadd2(uhA0[i], vhA0[i]), zero2);
            accA = __hfma2(xA, w2h[i], accA);
            __half2 xB = __hmax2(__hadd2(uhB0[i], vhB0[i]), zero2);
            accB = __hfma2(xB, w2h[i], accB);
        }
        #pragma unroll
        for (int i = 0; i < 4; i++) {
            __half2 xA = __hmax2(__hadd2(uhA1[i], vhA1[i]), zero2);
            accA = __hfma2(xA, w2h[4 + i], accA);
            __half2 xB = __hmax2(__hadd2(uhB1[i], vhB1[i]), zero2);
            accB = __hfma2(xB, w2h[4 + i], accB);
        }

        float2 fA = __half22float2(accA);
        float2 fB = __half22float2(accB);
        float pA = fA.x + fA.y;
        float pB = fB.x + fB.y;

        pA += __shfl_xor_sync(0xFFFFFFFFu, pA, 1);
        pB += __shfl_xor_sync(0xFFFFFFFFu, pB, 1);
        pA += __shfl_xor_sync(0xFFFFFFFFu, pA, 2);
        pB += __shfl_xor_sync(0xFFFFFFFFu, pB, 2);
        pA += __shfl_xor_sync(0xFFFFFFFFu, pA, 4);
        pB += __shfl_xor_sync(0xFFFFFFFFu, pB, 4);

        if (l8 == 0) {
            if (e < E) {
                float s2 = fmaxf(pA + c2, 0.f);
                float s3 = fmaxf(fmaf(s2, w3, c3), 0.f);
                out[e] = __fdividef(1.f, 1.f + __expf(-s3));
            }
            if (e2 < E) {
                float s2 = fmaxf(pB + c2, 0.f);
                float s3 = fmaxf(fmaf(s2, w3, c3), 0.f);
                out[e2] = __fdividef(1.f, 1.f + __expf(-s3));
            }
        }
    }
}

// ---------------------------------------------------------------------------
extern "C" void kernel_launch(void* const* d_in, const int* in_sizes, int n_in,
                              void* d_out, int out_size)
{
    const float* h   = (const float*)d_in[0];
    const int*   src = (const int*)  d_in[1];
    const int*   dst = (const int*)  d_in[2];
    const float* W1  = (const float*)d_in[3];
    const float* b1  = (const float*)d_in[4];
    const float* W2  = (const float*)d_in[5];
    const float* b2  = (const float*)d_in[6];
    const float* W3  = (const float*)d_in[7];
    const float* b3  = (const float*)d_in[8];
    float* out = (float*)d_out;

    const int n_nodes = in_sizes[0] / HID;
    const int E       = in_sizes[1];
    const int n_tiles = (n_nodes + TILE_M - 1) / TILE_M;

    cudaFuncSetAttribute(precompute_mma,
                         cudaFuncAttributeMaxDynamicSharedMemorySize, SMEM_BYTES);

    precompute_mma<<<K1_GRID, 256, SMEM_BYTES>>>(h, W1, b1, n_nodes, n_tiles);
    edge_kernel<<<4096, 256>>>(src, dst, W2, b2, W3, b3, out, E);
}

// round 11
// speedup vs baseline: 5.0737x; 1.0947x over previous
#include <cuda_runtime.h>
#include <cuda_fp16.h>
#include <math.h>
#include <stdint.h>

#define HID  128
#define NCOL 256
#define MAX_NODES 100000
#define TILE_M 64
#define PADK 136             // fp16 row stride in smem (272B -> conflict-free ldmatrix)
#define K1_GRID 296

// Y (fp16), 51.2 MB, L2-resident (evict_last policy). PERMUTED column layout (per half):
//   physical q = qnw*64 + qc*32 + qtig*8 + qnt4*2 + b
//   logical  j = qnw*64 + (qc*4+qnt4)*8 + qtig*2 + b
// b1/2 folded into both halves.
__device__ __half g_Yh[(size_t)MAX_NODES * NCOL];

#define A_ELEMS (TILE_M * PADK)     // 8704 halves (per buffer)
#define B_ELEMS (NCOL * PADK)       // 34816 halves
#define SMEM_BYTES ((2 * A_ELEMS + B_ELEMS) * 2 + 512)   // 104960 B -> 2 CTAs/SM

static __device__ __forceinline__ uint32_t packh2(float a, float b) {
    __half2 p = __floats2half2_rn(a, b);
    return *reinterpret_cast<uint32_t*>(&p);
}
static __device__ __forceinline__ uint32_t smem_u32(const void* p) {
    uint32_t a;
    asm("{ .reg .u64 t; cvta.to.shared.u64 t, %1; cvt.u32.u64 %0, t; }" : "=r"(a) : "l"(p));
    return a;
}
static __device__ __forceinline__ void hmma(float* d, const uint32_t* a, const uint32_t* b) {
    asm volatile(
        "mma.sync.aligned.m16n8k16.row.col.f32.f16.f16.f32 "
        "{%0,%1,%2,%3}, {%4,%5,%6,%7}, {%8,%9}, {%0,%1,%2,%3};"
        : "+f"(d[0]), "+f"(d[1]), "+f"(d[2]), "+f"(d[3])
        : "r"(a[0]), "r"(a[1]), "r"(a[2]), "r"(a[3]), "r"(b[0]), "r"(b[1]));
}
#define LDM_X4(r0, r1, r2, r3, addr) \
    asm volatile("ldmatrix.sync.aligned.m8n8.x4.shared.b16 {%0,%1,%2,%3}, [%4];" \
                 : "=r"(r0), "=r"(r1), "=r"(r2), "=r"(r3) : "r"(addr))

// L2 evict_last via access policy operand (works for any access width)
static __device__ __forceinline__ uint64_t evict_last_policy() {
    uint64_t p;
    asm("createpolicy.fractional.L2::evict_last.b64 %0, 1.0;" : "=l"(p));
    return p;
}
static __device__ __forceinline__ uint4 ldg_pol(const __half* p, uint64_t pol) {
    uint4 v;
    asm volatile("ld.global.L2::cache_hint.v4.u32 {%0,%1,%2,%3}, [%4], %5;"
                 : "=r"(v.x), "=r"(v.y), "=r"(v.z), "=r"(v.w) : "l"(p), "l"(pol));
    return v;
}
static __device__ __forceinline__ void stg_pol(__half* p, uint4 v, uint64_t pol) {
    asm volatile("st.global.L2::cache_hint.v4.u32 [%0], {%1,%2,%3,%4}, %5;"
                 :: "l"(p), "r"(v.x), "r"(v.y), "r"(v.z), "r"(v.w), "l"(pol) : "memory");
}

// ---------------------------------------------------------------------------
// K1: persistent, A double-buffered (register prefetch overlaps MMA).
// h read evict-first (__ldcs); Y written with evict_last policy.
// ---------------------------------------------------------------------------
__global__ __launch_bounds__(256, 2)
void precompute_mma(const float* __restrict__ h,
                    const float* __restrict__ W1,
                    const float* __restrict__ b1,
                    int n_nodes, int n_tiles)
{
    extern __shared__ __align__(16) uint16_t smem[];
    uint16_t* Ah  = smem;                       // 2 buffers of A_ELEMS
    uint16_t* Bh  = Ah + 2 * A_ELEMS;
    float*    b1s = reinterpret_cast<float*>(Bh + B_ELEMS);

    const int tid  = threadIdx.x;
    const int w    = tid >> 5;
    const int lane = tid & 31;
    const uint64_t pol = evict_last_policy();

    // ---- once per CTA: B (W1 repacked) + b1/2 ----
    #pragma unroll
    for (int idx = tid; idx < NCOL * 32; idx += 256) {
        const int r = idx >> 5, c = idx & 31;
        const float4* wr = reinterpret_cast<const float4*>(
            W1 + (size_t)(r & 127) * (2 * HID) + ((r >> 7) * HID));
        float4 f = wr[c];
        *reinterpret_cast<uint2*>(Bh + r * PADK + c * 4) =
            make_uint2(packh2(f.x, f.y), packh2(f.z, f.w));
    }
    if (tid < HID) b1s[tid] = b1[tid] * 0.5f;

    const int g   = lane >> 2;
    const int tig = lane & 3;
    const int mwarp = (w & 1) * 32;
    const int nwarp = (w >> 1) * 64;

    uint32_t a_addr0[2], b_addr[4];
    {
        const uint32_t sA = smem_u32(Ah), sB = smem_u32(Bh);
        #pragma unroll
        for (int mt = 0; mt < 2; mt++) {
            const int row = mwarp + mt * 16 + (lane & 15);
            a_addr0[mt] = sA + (uint32_t)(row * PADK + ((lane >> 4) & 1) * 8) * 2;
        }
        #pragma unroll
        for (int p = 0; p < 4; p++) {
            const int rn = nwarp + p * 16 + (lane & 7) + ((lane >> 4) & 1) * 8;
            b_addr[p] = sB + (uint32_t)(rn * PADK + ((lane >> 3) & 1) * 8) * 2;
        }
    }

    const float4* h4 = reinterpret_cast<const float4*>(h);
    const int c4   = tid & 31;
    const int row0 = tid >> 5;

    float4 pf[8];
    auto load_pf = [&](int tt) {
        #pragma unroll
        for (int k = 0; k < 8; k++) {
            const int m = tt * TILE_M + row0 + k * 8;
            pf[k] = (tt < n_tiles && m < n_nodes)
                  ? __ldcs(&h4[(size_t)m * 32 + c4])
                  : make_float4(0.f, 0.f, 0.f, 0.f);
        }
    };
    auto sts_pf = [&](uint16_t* buf) {
        #pragma unroll
        for (int k = 0; k < 8; k++)
            *reinterpret_cast<uint2*>(buf + (row0 + k * 8) * PADK + c4 * 4) =
                make_uint2(packh2(pf[k].x, pf[k].y), packh2(pf[k].z, pf[k].w));
    };

    int t = blockIdx.x;
    if (t < n_tiles) {
        load_pf(t);
        sts_pf(Ah);
    }
    __syncthreads();

    int buf = 0;
    while (t < n_tiles) {
        const int tn = t + (int)gridDim.x;
        load_pf(tn);                       // prefetch overlaps the MMA phase

        const uint32_t abase = (uint32_t)buf * (A_ELEMS * 2);
        float acc[2][8][4];
        #pragma unroll
        for (int mt = 0; mt < 2; mt++)
            #pragma unroll
            for (int nt = 0; nt < 8; nt++)
                #pragma unroll
                for (int r = 0; r < 4; r++) acc[mt][nt][r] = 0.f;

        #pragma unroll
        for (int kb = 0; kb < 8; kb++) {
            const uint32_t ko = (uint32_t)kb * 32;
            uint32_t ah[2][4];
            #pragma unroll
            for (int mt = 0; mt < 2; mt++)
                LDM_X4(ah[mt][0], ah[mt][1], ah[mt][2], ah[mt][3],
                       a_addr0[mt] + abase + ko);
            uint32_t bh[8][2];
            #pragma unroll
            for (int p = 0; p < 4; p++)
                LDM_X4(bh[2*p][0], bh[2*p][1], bh[2*p+1][0], bh[2*p+1][1], b_addr[p] + ko);
            #pragma unroll
            for (int mt = 0; mt < 2; mt++)
                #pragma unroll
                for (int nt = 0; nt < 8; nt++)
                    hmma(acc[mt][nt], ah[mt], bh[nt]);
        }

        // ---- epilogue: bias fold + permuted coalesced 16B stores (evict_last) ----
        const int m0 = t * TILE_M;
        #pragma unroll
        for (int mt = 0; mt < 2; mt++) {
            const int r0 = m0 + mwarp + mt * 16 + g;
            const int r1 = r0 + 8;
            #pragma unroll
            for (int c = 0; c < 2; c++) {
                uint4 s0, s1;
                __half2* h0 = reinterpret_cast<__half2*>(&s0);
                __half2* h1 = reinterpret_cast<__half2*>(&s1);
                #pragma unroll
                for (int q = 0; q < 4; q++) {
                    const int nt = c * 4 + q;
                    const int bcol = (nwarp + nt * 8 + tig * 2) & (HID - 1);
                    const float2 bb = *reinterpret_cast<const float2*>(&b1s[bcol]);
                    h0[q] = __floats2half2_rn(acc[mt][nt][0] + bb.x, acc[mt][nt][1] + bb.y);
                    h1[q] = __floats2half2_rn(acc[mt][nt][2] + bb.x, acc[mt][nt][3] + bb.y);
                }
                const uint32_t off = (uint32_t)nwarp + c * 32 + tig * 8;
                if (r0 < n_nodes) stg_pol(g_Yh + (size_t)r0 * NCOL + off, s0, pol);
                if (r1 < n_nodes) stg_pol(g_Yh + (size_t)r1 * NCOL + off, s1, pol);
            }
        }

        sts_pf(buf ? Ah : Ah + A_ELEMS);   // fill the other buffer
        __syncthreads();
        buf ^= 1;
        t = tn;
    }
}

// ---------------------------------------------------------------------------
// K2: 8 lanes/edge, 8 edges per warp-iteration, half2 math, evict_last Y loads.
// ---------------------------------------------------------------------------
__global__ __launch_bounds__(256)
void edge_kernel(const int* __restrict__ src,
                 const int* __restrict__ dst,
                 const float* __restrict__ W2,
                 const float* __restrict__ b2,
                 const float* __restrict__ W3,
                 const float* __restrict__ b3,
                 float* __restrict__ out,
                 int E)
{
    const int lane = threadIdx.x & 31;
    const int sub  = lane >> 3;
    const int l8   = lane & 7;
    const int wid  = (blockIdx.x * blockDim.x + threadIdx.x) >> 5;
    const int nwarps = (gridDim.x * blockDim.x) >> 5;
    const uint64_t pol = evict_last_policy();

    // lane features (physical within-half): i<4 -> q=l8*8+i*2 ; i>=4 -> q=64+l8*8+(i-4)*2
    __half2 w2h[8];
    #pragma unroll
    for (int i = 0; i < 8; i++) {
        const int q   = (i < 4) ? (l8 * 8 + i * 2) : (64 + l8 * 8 + (i - 4) * 2);
        const int qnw = q >> 6, qc = (q >> 5) & 1, qtig = (q >> 3) & 3, qnt4 = (q >> 1) & 3;
        const int j   = qnw * 64 + (qc * 4 + qnt4) * 8 + qtig * 2;
        w2h[i] = __floats2half2_rn(W2[j], W2[j + 1]);
    }
    const float c2 = b2[0];
    const float w3 = W3[0];
    const float c3 = b3[0];
    const __half2 zero2 = __floats2half2_rn(0.f, 0.f);

    for (int e = wid * 8 + sub; ; e += nwarps * 8) {
        const int ebase = e - sub;
        if (ebase >= E) break;
        const int eA = (e < E) ? e : (E - 1);
        const int e2 = e + 4;
        const int eB = (e2 < E) ? e2 : (E - 1);

        const int sA = src[eA], dA = dst[eA];
        const int sB = src[eB], dB = dst[eB];

        const __half* YA_u = g_Yh + (uint32_t)sA * NCOL;
        const __half* YA_v = g_Yh + (uint32_t)dA * NCOL + HID;
        const __half* YB_u = g_Yh + (uint32_t)sB * NCOL;
        const __half* YB_v = g_Yh + (uint32_t)dB * NCOL + HID;

        uint4 ua0 = ldg_pol(YA_u + l8 * 8, pol);
        uint4 ua1 = ldg_pol(YA_u + 64 + l8 * 8, pol);
        uint4 va0 = ldg_pol(YA_v + l8 * 8, pol);
        uint4 va1 = ldg_pol(YA_v + 64 + l8 * 8, pol);
        uint4 ub0 = ldg_pol(YB_u + l8 * 8, pol);
        uint4 ub1 = ldg_pol(YB_u + 64 + l8 * 8, pol);
        uint4 vb0 = ldg_pol(YB_v + l8 * 8, pol);
        uint4 vb1 = ldg_pol(YB_v + 64 + l8 * 8, pol);

        const __half2* uhA0 = reinterpret_cast<const __half2*>(&ua0);
        const __half2* uhA1 = reinterpret_cast<const __half2*>(&ua1);
        const __half2* vhA0 = reinterpret_cast<const __half2*>(&va0);
        const __half2* vhA1 = reinterpret_cast<const __half2*>(&va1);
        const __half2* uhB0 = reinterpret_cast<const __half2*>(&ub0);
        const __half2* uhB1 = reinterpret_cast<const __half2*>(&ub1);
        const __half2* vhB0 = reinterpret_cast<const __half2*>(&vb0);
        const __half2* vhB1 = reinterpret_cast<const __half2*>(&vb1);

        __half2 accA = zero2, accB = zero2;
        #pragma unroll
        for (int i = 0; i < 4; i++) {
            __half2 xA = __hmax2(__hadd2(uhA0[i], vhA0[i]), zero2);
            accA = __hfma2(xA, w2h[i], accA);
            __half2 xB = __hmax2(__hadd2(uhB0[i], vhB0[i]), zero2);
            accB = __hfma2(xB, w2h[i], accB);
        }
        #pragma unroll
        for (int i = 0; i < 4; i++) {
            __half2 xA = __hmax2(__hadd2(uhA1[i], vhA1[i]), zero2);
            accA = __hfma2(xA, w2h[4 + i], accA);
            __half2 xB = __hmax2(__hadd2(uhB1[i], vhB1[i]), zero2);
            accB = __hfma2(xB, w2h[4 + i], accB);
        }

        float2 fA = __half22float2(accA);
        float2 fB = __half22float2(accB);
        float pA = fA.x + fA.y;
        float pB = fB.x + fB.y;

        pA += __shfl_xor_sync(0xFFFFFFFFu, pA, 1);
        pB += __shfl_xor_sync(0xFFFFFFFFu, pB, 1);
        pA += __shfl_xor_sync(0xFFFFFFFFu, pA, 2);
        pB += __shfl_xor_sync(0xFFFFFFFFu, pB, 2);
        pA += __shfl_xor_sync(0xFFFFFFFFu, pA, 4);
        pB += __shfl_xor_sync(0xFFFFFFFFu, pB, 4);

        if (l8 == 0) {
            if (e < E) {
                float s2 = fmaxf(pA + c2, 0.f);
                float s3 = fmaxf(fmaf(s2, w3, c3), 0.f);
                __stcs(&out[e], __fdividef(1.f, 1.f + __expf(-s3)));
            }
            if (e2 < E) {
                float s2 = fmaxf(pB + c2, 0.f);
                float s3 = fmaxf(fmaf(s2, w3, c3), 0.f);
                __stcs(&out[e2], __fdividef(1.f, 1.f + __expf(-s3)));
            }
        }
    }
}

// ---------------------------------------------------------------------------
extern "C" void kernel_launch(void* const* d_in, const int* in_sizes, int n_in,
                              void* d_out, int out_size)
{
    const float* h   = (const float*)d_in[0];
    const int*   src = (const int*)  d_in[1];
    const int*   dst = (const int*)  d_in[2];
    const float* W1  = (const float*)d_in[3];
    const float* b1  = (const float*)d_in[4];
    const float* W2  = (const float*)d_in[5];
    const float* b2  = (const float*)d_in[6];
    const float* W3  = (const float*)d_in[7];
    const float* b3  = (const float*)d_in[8];
    float* out = (float*)d_out;

    const int n_nodes = in_sizes[0] / HID;
    const int E       = in_sizes[1];
    const int n_tiles = (n_nodes + TILE_M - 1) / TILE_M;

    cudaFuncSetAttribute(precompute_mma,
                         cudaFuncAttributeMaxDynamicSharedMemorySize, SMEM_BYTES);

    precompute_mma<<<K1_GRID, 256, SMEM_BYTES>>>(h, W1, b1, n_nodes, n_tiles);
    edge_kernel<<<4096, 256>>>(src, dst, W2, b2, W3, b3, out, E);
}

// round 12
// speedup vs baseline: 5.2402x; 1.0328x over previous
#include <cuda_runtime.h>
#include <cuda_fp16.h>
#include <math.h>
#include <stdint.h>

#define HID  128
#define NCOL 256
#define MAX_NODES 100000
#define TILE_M 64
#define PADK 136             // fp16 row stride in smem (272B -> conflict-free ldmatrix)
#define K1_GRID 296

// Y (fp16), 51.2 MB. PERMUTED column layout (per 128-col half):
//   physical q = qnw*64 + qc*32 + qtig*8 + qnt4*2 + b
//   logical  j = qnw*64 + (qc*4+qnt4)*8 + qtig*2 + b
// b1/2 folded into both halves.
__device__ __half g_Yh[(size_t)MAX_NODES * NCOL];

#define A_ELEMS (TILE_M * PADK)     // 8704 halves (per buffer)
#define B_ELEMS (NCOL * PADK)       // 34816 halves
#define SMEM_BYTES ((2 * A_ELEMS + B_ELEMS) * 2 + 512)   // 104960 B -> 2 CTAs/SM

static __device__ __forceinline__ uint32_t packh2(float a, float b) {
    __half2 p = __floats2half2_rn(a, b);
    return *reinterpret_cast<uint32_t*>(&p);
}
static __device__ __forceinline__ uint32_t smem_u32(const void* p) {
    uint32_t a;
    asm("{ .reg .u64 t; cvta.to.shared.u64 t, %1; cvt.u32.u64 %0, t; }" : "=r"(a) : "l"(p));
    return a;
}
static __device__ __forceinline__ void hmma(float* d, const uint32_t* a, const uint32_t* b) {
    asm volatile(
        "mma.sync.aligned.m16n8k16.row.col.f32.f16.f16.f32 "
        "{%0,%1,%2,%3}, {%4,%5,%6,%7}, {%8,%9}, {%0,%1,%2,%3};"
        : "+f"(d[0]), "+f"(d[1]), "+f"(d[2]), "+f"(d[3])
        : "r"(a[0]), "r"(a[1]), "r"(a[2]), "r"(a[3]), "r"(b[0]), "r"(b[1]));
}
#define LDM_X4(r0, r1, r2, r3, addr) \
    asm volatile("ldmatrix.sync.aligned.m8n8.x4.shared.b16 {%0,%1,%2,%3}, [%4];" \
                 : "=r"(r0), "=r"(r1), "=r"(r2), "=r"(r3) : "r"(addr))

// ---------------------------------------------------------------------------
// K1: persistent, A double-buffered (register prefetch overlaps MMA).
// ---------------------------------------------------------------------------
__global__ __launch_bounds__(256, 2)
void precompute_mma(const float* __restrict__ h,
                    const float* __restrict__ W1,
                    const float* __restrict__ b1,
                    int n_nodes, int n_tiles)
{
    extern __shared__ __align__(16) uint16_t smem[];
    uint16_t* Ah  = smem;                       // 2 buffers of A_ELEMS
    uint16_t* Bh  = Ah + 2 * A_ELEMS;
    float*    b1s = reinterpret_cast<float*>(Bh + B_ELEMS);

    const int tid  = threadIdx.x;
    const int w    = tid >> 5;
    const int lane = tid & 31;

    // ---- once per CTA: B (W1 repacked) + b1/2 ----
    #pragma unroll
    for (int idx = tid; idx < NCOL * 32; idx += 256) {
        const int r = idx >> 5, c = idx & 31;
        const float4* wr = reinterpret_cast<const float4*>(
            W1 + (size_t)(r & 127) * (2 * HID) + ((r >> 7) * HID));
        float4 f = wr[c];
        *reinterpret_cast<uint2*>(Bh + r * PADK + c * 4) =
            make_uint2(packh2(f.x, f.y), packh2(f.z, f.w));
    }
    if (tid < HID) b1s[tid] = b1[tid] * 0.5f;

    const int g   = lane >> 2;
    const int tig = lane & 3;
    const int mwarp = (w & 1) * 32;
    const int nwarp = (w >> 1) * 64;

    uint32_t a_addr0[2], b_addr[4];
    {
        const uint32_t sA = smem_u32(Ah), sB = smem_u32(Bh);
        #pragma unroll
        for (int mt = 0; mt < 2; mt++) {
            const int row = mwarp + mt * 16 + (lane & 15);
            a_addr0[mt] = sA + (uint32_t)(row * PADK + ((lane >> 4) & 1) * 8) * 2;
        }
        #pragma unroll
        for (int p = 0; p < 4; p++) {
            const int rn = nwarp + p * 16 + (lane & 7) + ((lane >> 4) & 1) * 8;
            b_addr[p] = sB + (uint32_t)(rn * PADK + ((lane >> 3) & 1) * 8) * 2;
        }
    }

    const float4* h4 = reinterpret_cast<const float4*>(h);
    const int c4   = tid & 31;
    const int row0 = tid >> 5;

    float4 pf[8];
    auto load_pf = [&](int tt) {
        #pragma unroll
        for (int k = 0; k < 8; k++) {
            const int m = tt * TILE_M + row0 + k * 8;
            pf[k] = (tt < n_tiles && m < n_nodes)
                  ? __ldcs(&h4[(size_t)m * 32 + c4])
                  : make_float4(0.f, 0.f, 0.f, 0.f);
        }
    };
    auto sts_pf = [&](uint16_t* buf) {
        #pragma unroll
        for (int k = 0; k < 8; k++)
            *reinterpret_cast<uint2*>(buf + (row0 + k * 8) * PADK + c4 * 4) =
                make_uint2(packh2(pf[k].x, pf[k].y), packh2(pf[k].z, pf[k].w));
    };

    int t = blockIdx.x;
    if (t < n_tiles) {
        load_pf(t);
        sts_pf(Ah);
    }
    __syncthreads();

    int buf = 0;
    while (t < n_tiles) {
        const int tn = t + (int)gridDim.x;
        load_pf(tn);                       // prefetch overlaps the MMA phase

        const uint32_t abase = (uint32_t)buf * (A_ELEMS * 2);
        float acc[2][8][4];
        #pragma unroll
        for (int mt = 0; mt < 2; mt++)
            #pragma unroll
            for (int nt = 0; nt < 8; nt++)
                #pragma unroll
                for (int r = 0; r < 4; r++) acc[mt][nt][r] = 0.f;

        #pragma unroll
        for (int kb = 0; kb < 8; kb++) {
            const uint32_t ko = (uint32_t)kb * 32;
            uint32_t ah[2][4];
            #pragma unroll
            for (int mt = 0; mt < 2; mt++)
                LDM_X4(ah[mt][0], ah[mt][1], ah[mt][2], ah[mt][3],
                       a_addr0[mt] + abase + ko);
            uint32_t bh[8][2];
            #pragma unroll
            for (int p = 0; p < 4; p++)
                LDM_X4(bh[2*p][0], bh[2*p][1], bh[2*p+1][0], bh[2*p+1][1], b_addr[p] + ko);
            #pragma unroll
            for (int mt = 0; mt < 2; mt++)
                #pragma unroll
                for (int nt = 0; nt < 8; nt++)
                    hmma(acc[mt][nt], ah[mt], bh[nt]);
        }

        // ---- epilogue: bias fold + permuted coalesced 16B stores ----
        const int m0 = t * TILE_M;
        #pragma unroll
        for (int mt = 0; mt < 2; mt++) {
            const int r0 = m0 + mwarp + mt * 16 + g;
            const int r1 = r0 + 8;
            #pragma unroll
            for (int c = 0; c < 2; c++) {
                uint4 s0, s1;
                __half2* h0 = reinterpret_cast<__half2*>(&s0);
                __half2* h1 = reinterpret_cast<__half2*>(&s1);
                #pragma unroll
                for (int q = 0; q < 4; q++) {
                    const int nt = c * 4 + q;
                    const int bcol = (nwarp + nt * 8 + tig * 2) & (HID - 1);
                    const float2 bb = *reinterpret_cast<const float2*>(&b1s[bcol]);
                    h0[q] = __floats2half2_rn(acc[mt][nt][0] + bb.x, acc[mt][nt][1] + bb.y);
                    h1[q] = __floats2half2_rn(acc[mt][nt][2] + bb.x, acc[mt][nt][3] + bb.y);
                }
                const uint32_t off = (uint32_t)nwarp + c * 32 + tig * 8;
                if (r0 < n_nodes)
                    *reinterpret_cast<uint4*>(g_Yh + (size_t)r0 * NCOL + off) = s0;
                if (r1 < n_nodes)
                    *reinterpret_cast<uint4*>(g_Yh + (size_t)r1 * NCOL + off) = s1;
            }
        }

        sts_pf(buf ? Ah : Ah + A_ELEMS);   // fill the other buffer
        __syncthreads();
        buf ^= 1;
        t = tn;
    }
}

// ---------------------------------------------------------------------------
// K2: 8 lanes/edge, 8 edges per warp-iteration, half2 math, plain vector loads.
// __launch_bounds__(256, 6): regs<=42 -> 6 CTAs/SM -> 75% occupancy ceiling.
// ---------------------------------------------------------------------------
__global__ __launch_bounds__(256, 6)
void edge_kernel(const int* __restrict__ src,
                 const int* __restrict__ dst,
                 const float* __restrict__ W2,
                 const float* __restrict__ b2,
                 const float* __restrict__ W3,
                 const float* __restrict__ b3,
                 float* __restrict__ out,
                 int E)
{
    const int lane = threadIdx.x & 31;
    const int sub  = lane >> 3;
    const int l8   = lane & 7;
    const int wid  = (blockIdx.x * blockDim.x + threadIdx.x) >> 5;
    const int nwarps = (gridDim.x * blockDim.x) >> 5;

    // lane features (physical within-half): i<4 -> q=l8*8+i*2 ; i>=4 -> q=64+l8*8+(i-4)*2
    __half2 w2h[8];
    #pragma unroll
    for (int i = 0; i < 8; i++) {
        const int q   = (i < 4) ? (l8 * 8 + i * 2) : (64 + l8 * 8 + (i - 4) * 2);
        const int qnw = q >> 6, qc = (q >> 5) & 1, qtig = (q >> 3) & 3, qnt4 = (q >> 1) & 3;
        const int j   = qnw * 64 + (qc * 4 + qnt4) * 8 + qtig * 2;
        w2h[i] = __floats2half2_rn(W2[j], W2[j + 1]);
    }
    const float c2 = b2[0];
    const float w3 = W3[0];
    const float c3 = b3[0];
    const __half2 zero2 = __floats2half2_rn(0.f, 0.f);

    for (int e = wid * 8 + sub; ; e += nwarps * 8) {
        const int ebase = e - sub;
        if (ebase >= E) break;
        const int eA = (e < E) ? e : (E - 1);
        const int e2 = e + 4;
        const int eB = (e2 < E) ? e2 : (E - 1);

        const int sA = src[eA], dA = dst[eA];
        const int sB = src[eB], dB = dst[eB];

        const __half* YA_u = g_Yh + (uint32_t)sA * NCOL;
        const __half* YA_v = g_Yh + (uint32_t)dA * NCOL + HID;
        const __half* YB_u = g_Yh + (uint32_t)sB * NCOL;
        const __half* YB_v = g_Yh + (uint32_t)dB * NCOL + HID;

        uint4 ua0 = *reinterpret_cast<const uint4*>(YA_u + l8 * 8);
        uint4 ua1 = *reinterpret_cast<const uint4*>(YA_u + 64 + l8 * 8);
        uint4 va0 = *reinterpret_cast<const uint4*>(YA_v + l8 * 8);
        uint4 va1 = *reinterpret_cast<const uint4*>(YA_v + 64 + l8 * 8);
        uint4 ub0 = *reinterpret_cast<const uint4*>(YB_u + l8 * 8);
        uint4 ub1 = *reinterpret_cast<const uint4*>(YB_u + 64 + l8 * 8);
        uint4 vb0 = *reinterpret_cast<const uint4*>(YB_v + l8 * 8);
        uint4 vb1 = *reinterpret_cast<const uint4*>(YB_v + 64 + l8 * 8);

        const __half2* uhA0 = reinterpret_cast<const __half2*>(&ua0);
        const __half2* uhA1 = reinterpret_cast<const __half2*>(&ua1);
        const __half2* vhA0 = reinterpret_cast<const __half2*>(&va0);
        const __half2* vhA1 = reinterpret_cast<const __half2*>(&va1);
        const __half2* uhB0 = reinterpret_cast<const __half2*>(&ub0);
        const __half2* uhB1 = reinterpret_cast<const __half2*>(&ub1);
        const __half2* vhB0 = reinterpret_cast<const __half2*>(&vb0);
        const __half2* vhB1 = reinterpret_cast<const __half2*>(&vb1);

        __half2 accA = zero2, accB = zero2;
        #pragma unroll
        for (int i = 0; i < 4; i++) {
            __half2 xA = __hmax2(__hadd2(uhA0[i], vhA0[i]), zero2);
            accA = __hfma2(xA, w2h[i], accA);
            __half2 xB = __hmax2(__hadd2(uhB0[i], vhB0[i]), zero2);
            accB = __hfma2(xB, w2h[i], accB);
        }
        #pragma unroll
        for (int i = 0; i < 4; i++) {
            __half2 xA = __hmax2(__hadd2(uhA1[i], vhA1[i]), zero2);
            accA = __hfma2(xA, w2h[4 + i], accA);
            __half2 xB = __hmax2(__hadd2(uhB1[i], vhB1[i]), zero2);
            accB = __hfma2(xB, w2h[4 + i], accB);
        }

        float2 fA = __half22float2(accA);
        float2 fB = __half22float2(accB);
        float pA = fA.x + fA.y;
        float pB = fB.x + fB.y;

        pA += __shfl_xor_sync(0xFFFFFFFFu, pA, 1);
        pB += __shfl_xor_sync(0xFFFFFFFFu, pB, 1);
        pA += __shfl_xor_sync(0xFFFFFFFFu, pA, 2);
        pB += __shfl_xor_sync(0xFFFFFFFFu, pB, 2);
        pA += __shfl_xor_sync(0xFFFFFFFFu, pA, 4);
        pB += __shfl_xor_sync(0xFFFFFFFFu, pB, 4);

        if (l8 == 0) {
            if (e < E) {
                float s2 = fmaxf(pA + c2, 0.f);
                float s3 = fmaxf(fmaf(s2, w3, c3), 0.f);
                __stcs(&out[e], __fdividef(1.f, 1.f + __expf(-s3)));
            }
            if (e2 < E) {
                float s2 = fmaxf(pB + c2, 0.f);
                float s3 = fmaxf(fmaf(s2, w3, c3), 0.f);
                __stcs(&out[e2], __fdividef(1.f, 1.f + __expf(-s3)));
            }
        }
    }
}

// ---------------------------------------------------------------------------
extern "C" void kernel_launch(void* const* d_in, const int* in_sizes, int n_in,
                              void* d_out, int out_size)
{
    const float* h   = (const float*)d_in[0];
    const int*   src = (const int*)  d_in[1];
    const int*   dst = (const int*)  d_in[2];
    const float* W1  = (const float*)d_in[3];
    const float* b1  = (const float*)d_in[4];
    const float* W2  = (const float*)d_in[5];
    const float* b2  = (const float*)d_in[6];
    const float* W3  = (const float*)d_in[7];
    const float* b3  = (const float*)d_in[8];
    float* out = (float*)d_out;

    const int n_nodes = in_sizes[0] / HID;
    const int E       = in_sizes[1];
    const int n_tiles = (n_nodes + TILE_M - 1) / TILE_M;

    cudaFuncSetAttribute(precompute_mma,
                         cudaFuncAttributeMaxDynamicSharedMemorySize, SMEM_BYTES);

    precompute_mma<<<K1_GRID, 256, SMEM_BYTES>>>(h, W1, b1, n_nodes, n_tiles);
    edge_kernel<<<4096, 256>>>(src, dst, W2, b2, W3, b3, out, E);
}